// round 11
// baseline (speedup 1.0000x reference)
#include <cuda_runtime.h>
#include <cuda_fp16.h>
#include <math.h>
#include <stdint.h>

#define Bq    32
#define Lq    512
#define Dq    768
#define HIDq  192
#define DIq   1536
#define DSq   16
#define DTRq  48
#define Nq    (Bq*Lq)        // 16384
#define EPSq  1e-5f

// ---------------- scratch ----------------
__device__ __align__(256) float  g_h0  [Nq*HIDq];
__device__ __align__(256) float  g_tmpH[Nq*HIDq];
__device__ __align__(256) __half g_h2  [Nq*HIDq];
__device__ __align__(256) float  g_e   [Nq*Dq];
__device__ __align__(256) float  g_x1  [Nq*Dq];
__device__ __align__(256) __half g_xn  [Nq*Dq];
__device__ __align__(256) float  g_xz  [Nq*2*DIq];
__device__ __align__(256) __half g_xm2 [Nq*DIq];
__device__ __align__(256) __half g_dbc [Nq*80];
__device__ __align__(256) float  g_del [Nq*DIq];
__device__ __align__(256) __half g_y   [Nq*DIq];
__device__ __align__(256) float  g_mo  [Nq*Dq];
__device__ __align__(256) float  g_gl  [Nq*Dq];
__device__ __align__(256) float  g_xf  [Nq*Dq];
__device__ __align__(256) float  g_rm  [Nq];
__device__ __align__(256) float  g_rs  [Nq];
__device__ __align__(256) float  g_rm2 [Nq];
__device__ __align__(256) float  g_rs2 [Nq];
__device__ __align__(256) float  g_fid [Bq*Dq];
__device__ __align__(256) __half g_xr  [Nq*Dq];     // x as fp16
// fp16 weights, concatenated
#define W_SQ   0
#define W_EX   (W_SQ  + HIDq*Dq)
#define W_INP  (W_EX  + Dq*HIDq)
#define W_XP   (W_INP + 2*DIq*Dq)
#define W_DT   (W_XP  + 80*DIq)
#define W_OUT  (W_DT  + DIq*DTRq)
#define W_GATE (W_OUT + Dq*DIq)
#define W_TOT  (W_GATE + Dq*Dq)
__device__ __align__(256) __half g_wh[W_TOT];
#define ST_SUM1   0
#define ST_SQ1    (ST_SUM1+192)
#define ST_SUM2   (ST_SQ1+192)
#define ST_SQ2    (ST_SUM2+192)
#define ST_SUM3   (ST_SQ2+192)
#define ST_SQ3    (ST_SUM3+768)
#define ST_TOTAL  (ST_SQ3+768)
__device__ __align__(256) float g_stats[ST_TOTAL];

// ================= helpers =================
__device__ __forceinline__ void mma_f16(float* d, const uint32_t* a, const uint32_t* b) {
    asm volatile(
        "mma.sync.aligned.m16n8k16.row.col.f32.f16.f16.f32 "
        "{%0,%1,%2,%3}, {%4,%5,%6,%7}, {%8,%9}, {%0,%1,%2,%3};"
        : "+f"(d[0]), "+f"(d[1]), "+f"(d[2]), "+f"(d[3])
        : "r"(a[0]), "r"(a[1]), "r"(a[2]), "r"(a[3]), "r"(b[0]), "r"(b[1]));
}

__device__ __forceinline__ uint32_t smem_u32(const void* p) {
    uint32_t a;
    asm("{ .reg .u64 t; cvta.to.shared.u64 t, %1; cvt.u32.u64 %0, t; }" : "=r"(a) : "l"(p));
    return a;
}
#define CP_ASYNC(dst, src, sz) \
    asm volatile("cp.async.cg.shared.global [%0], [%1], 16, %2;" \
                 :: "r"(dst), "l"(src), "r"(sz) : "memory")
#define CP_COMMIT() asm volatile("cp.async.commit_group;" ::: "memory")
#define CP_WAIT(n)  asm volatile("cp.async.wait_group %0;" :: "n"(n) : "memory")

// ================= FP16 GEMM: cp.async staged, 2 CTAs/SM =================
// C[M,Nc] = A[M,K](lda) @ W[Nc,K]^T (A, W __half; fp32 accum). C row stride ldc.
// MODE 0: float store. MODE 1: float softplus(v+p0[c]). MODE 2: __half store.
// smem tile: 128 rows x 32 halfs (16 u32), padded stride SH=20 u32.
#define SH 20
#define TILE_U16 (128*SH)
#define GEMM_DSMEM (2*2*TILE_U16*4)

template<int MODE>
__global__ void __launch_bounds__(256, 2) gemm_tc(
    const __half* __restrict__ A, int lda,
    const __half* __restrict__ W,
    float* __restrict__ C, int Nc, int ldc, int K,
    const float* __restrict__ p0)
{
    extern __shared__ uint32_t dsm[];
    const uint32_t sbase = smem_u32(dsm);

    const int bm = blockIdx.y * 128;
    const int bn = blockIdx.x * 128;
    const int t  = threadIdx.x;
    const int wid  = t >> 5;
    const int lane = t & 31;
    const int qr = lane >> 2;
    const int qc = lane & 3;
    const int warp_m = wid & 3;
    const int warp_n = wid >> 2;

    // cp.async mapping: each thread copies 16B (8 halfs) for rows r0t, r0t+64
    const int r0t = t >> 2;            // 0..63
    const int c8  = (t & 3) * 8;       // half col 0,8,16,24

    const __half* aRow[2];
    const __half* bRow[2];
    int bOk[2];
    uint32_t dstOff[2];
    #pragma unroll
    for (int i = 0; i < 2; i++) {
        int r = r0t + i*64;
        aRow[i] = A + (size_t)(bm + r)*lda;
        int j = bn + r;
        bOk[i] = (j < Nc);
        bRow[i] = W + (size_t)(bOk[i] ? j : 0)*K;
        dstOff[i] = (uint32_t)(r*SH + (t&3)*4) * 4u;   // bytes
    }

    float acc[2][8][4];
    #pragma unroll
    for (int mt = 0; mt < 2; mt++)
        #pragma unroll
        for (int nt = 0; nt < 8; nt++)
            #pragma unroll
            for (int q = 0; q < 4; q++) acc[mt][nt][q] = 0.f;

    const int NC = (K + 31) / 32;

    // prologue: chunk 0 -> stage 0
    {
        int k = c8;
        int szA = (k < K) ? 16 : 0;
        #pragma unroll
        for (int i = 0; i < 2; i++)
            CP_ASYNC(sbase + dstOff[i], aRow[i] + k, szA);
        #pragma unroll
        for (int i = 0; i < 2; i++) {
            int szB = (bOk[i] && k < K) ? 16 : 0;
            CP_ASYNC(sbase + (uint32_t)TILE_U16*4 + dstOff[i], bRow[i] + k, szB);
        }
        CP_COMMIT();
    }

    for (int ch = 0; ch < NC; ch++) {
        const int buf = ch & 1;
        if (ch + 1 < NC) {
            const int k = (ch + 1)*32 + c8;
            uint32_t base = sbase + (uint32_t)(buf ^ 1) * 2u * TILE_U16 * 4u;
            int szA = (k < K) ? 16 : 0;
            #pragma unroll
            for (int i = 0; i < 2; i++)
                CP_ASYNC(base + dstOff[i], aRow[i] + k, szA);
            #pragma unroll
            for (int i = 0; i < 2; i++) {
                int szB = (bOk[i] && k < K) ? 16 : 0;
                CP_ASYNC(base + (uint32_t)TILE_U16*4 + dstOff[i], bRow[i] + k, szB);
            }
            CP_COMMIT();
            CP_WAIT(1);
        } else {
            CP_WAIT(0);
        }
        __syncthreads();

        const uint32_t* As = dsm + (size_t)buf * 2 * TILE_U16;
        const uint32_t* Bs = As + TILE_U16;
        #pragma unroll
        for (int ks = 0; ks < 2; ks++) {       // 2 x k16
            const int kb = ks * 8;             // u32 col base
            uint32_t afr[2][4];
            #pragma unroll
            for (int mt = 0; mt < 2; mt++) {
                int r0 = warp_m*32 + mt*16 + qr;
                afr[mt][0] = As[r0*SH + kb + qc];
                afr[mt][1] = As[(r0+8)*SH + kb + qc];
                afr[mt][2] = As[r0*SH + kb + 4 + qc];
                afr[mt][3] = As[(r0+8)*SH + kb + 4 + qc];
            }
            uint32_t bfr[8][2];
            #pragma unroll
            for (int nt = 0; nt < 8; nt++) {
                int n = warp_n*64 + nt*8 + qr;
                bfr[nt][0] = Bs[n*SH + kb + qc];
                bfr[nt][1] = Bs[n*SH + kb + 4 + qc];
            }
            #pragma unroll
            for (int mt = 0; mt < 2; mt++)
                #pragma unroll
                for (int nt = 0; nt < 8; nt++)
                    mma_f16(acc[mt][nt], afr[mt], bfr[nt]);
        }
        __syncthreads();
    }

    if (MODE == 0) {
        #pragma unroll
        for (int mt = 0; mt < 2; mt++) {
            int r0 = bm + warp_m*32 + mt*16 + qr;
            #pragma unroll
            for (int nt = 0; nt < 8; nt++) {
                int c = bn + warp_n*64 + nt*8 + qc*2;
                if (c < Nc) {
                    *(float2*)&C[(size_t)r0*ldc + c]     = make_float2(acc[mt][nt][0], acc[mt][nt][1]);
                    *(float2*)&C[(size_t)(r0+8)*ldc + c] = make_float2(acc[mt][nt][2], acc[mt][nt][3]);
                }
            }
        }
    } else if (MODE == 1) {
        #pragma unroll
        for (int mt = 0; mt < 2; mt++) {
            int r0 = bm + warp_m*32 + mt*16 + qr;
            #pragma unroll
            for (int nt = 0; nt < 8; nt++) {
                int c = bn + warp_n*64 + nt*8 + qc*2;
                if (c < Nc) {
                    float b0 = p0[c], b1 = p0[c+1];
                    float v;
                    v = acc[mt][nt][0] + b0; v = (v > 20.f) ? v : log1pf(__expf(v));
                    C[(size_t)r0*ldc + c] = v;
                    v = acc[mt][nt][1] + b1; v = (v > 20.f) ? v : log1pf(__expf(v));
                    C[(size_t)r0*ldc + c + 1] = v;
                    v = acc[mt][nt][2] + b0; v = (v > 20.f) ? v : log1pf(__expf(v));
                    C[(size_t)(r0+8)*ldc + c] = v;
                    v = acc[mt][nt][3] + b1; v = (v > 20.f) ? v : log1pf(__expf(v));
                    C[(size_t)(r0+8)*ldc + c + 1] = v;
                }
            }
        }
    } else {
        __half* C2 = (__half*)C;
        #pragma unroll
        for (int mt = 0; mt < 2; mt++) {
            int r0 = bm + warp_m*32 + mt*16 + qr;
            #pragma unroll
            for (int nt = 0; nt < 8; nt++) {
                int c = bn + warp_n*64 + nt*8 + qc*2;
                if (c < Nc) {
                    *(__half2*)&C2[(size_t)r0*ldc + c] =
                        __floats2half2_rn(acc[mt][nt][0], acc[mt][nt][1]);
                    *(__half2*)&C2[(size_t)(r0+8)*ldc + c] =
                        __floats2half2_rn(acc[mt][nt][2], acc[mt][nt][3]);
                }
            }
        }
    }
}

// ---------------- f32 -> f16 convert (4 elems/thread) ----------------
__global__ void cvt_f16(const float* __restrict__ X, __half* __restrict__ Y, int n4)
{
    int i = blockIdx.x * blockDim.x + threadIdx.x;
    if (i >= n4) return;
    float4 v = ((const float4*)X)[i];
    __half2 h0 = __floats2half2_rn(v.x, v.y);
    __half2 h1 = __floats2half2_rn(v.z, v.w);
    ((__half2*)Y)[2*i]   = h0;
    ((__half2*)Y)[2*i+1] = h1;
}

// ---------------- BatchNorm stats ----------------
__global__ void bn_stats(const float* __restrict__ X, int M, int C,
                         float* __restrict__ sum, float* __restrict__ sq)
{
    int c = blockIdx.y * blockDim.x + threadIdx.x;
    if (c >= C) return;
    int rows = M / gridDim.x;
    int r0 = blockIdx.x * rows;
    float s = 0.f, ss = 0.f;
    for (int r = r0; r < r0 + rows; r++) {
        float v = X[(size_t)r*C + c];
        s += v; ss += v*v;
    }
    atomicAdd(&sum[c], s);
    atomicAdd(&sq[c],  ss);
}

// bn+silu; HALF selects output type
template<bool HALF>
__global__ void bn_silu(const float* __restrict__ X, void* __restrict__ Yv,
                        const float* __restrict__ sum, const float* __restrict__ sq,
                        const float* __restrict__ g, const float* __restrict__ b,
                        int M, int C)
{
    int idx = blockIdx.x * blockDim.x + threadIdx.x;
    if (idx >= M*C) return;
    int c = idx % C;
    float mean = sum[c] / (float)M;
    float var  = sq[c] / (float)M - mean*mean;
    float v = (X[idx] - mean) * rsqrtf(var + EPSq) * g[c] + b[c];
    v = v / (1.f + __expf(-v));
    if (HALF) ((__half*)Yv)[idx] = __float2half_rn(v);
    else      ((float*)Yv)[idx]  = v;
}

// ---------------- depthwise conv K=5 ----------------
__global__ void dwconv5(const float* __restrict__ X, const float* __restrict__ w,
                        float* __restrict__ Y)
{
    int idx = blockIdx.x * blockDim.x + threadIdx.x;
    if (idx >= Nq*HIDq) return;
    int c  = idx % HIDq;
    int l  = (idx / HIDq) % Lq;
    int bb = idx / (HIDq*Lq);
    const float* xb = X + (size_t)bb*Lq*HIDq;
    float acc = 0.f;
    #pragma unroll
    for (int k = 0; k < 5; k++) {
        int ls = l - 2 + k;
        if (ls >= 0 && ls < Lq) acc += xb[(size_t)ls*HIDq + c] * w[c*5 + k];
    }
    Y[idx] = acc;
}

// ---------------- bn_add + LN, fused (xn stored fp16) ----------------
__global__ void __launch_bounds__(256) bn_add_ln(
    const float* __restrict__ E, const float* __restrict__ X,
    const float* __restrict__ sum3, const float* __restrict__ sq3,
    const float* __restrict__ exg, const float* __restrict__ exb,
    const float* __restrict__ lng, const float* __restrict__ lnb,
    float* __restrict__ X1, __half* __restrict__ XN,
    float* __restrict__ rm, float* __restrict__ rs)
{
    const int row = blockIdx.x;
    const int tid = threadIdx.x;
    float vloc[3];
    float s = 0.f, ss = 0.f;
    #pragma unroll
    for (int j = 0; j < 3; j++) {
        int c = tid + j*256;
        float mean = sum3[c] / (float)Nq;
        float var  = sq3[c] / (float)Nq - mean*mean;
        float ga = rsqrtf(var + EPSq) * exg[c];
        float be = exb[c] - mean*ga;
        float v = X[(size_t)row*Dq + c] + E[(size_t)row*Dq + c]*ga + be;
        vloc[j] = v;
        s += v; ss += v*v;
    }
    __shared__ float sh1[8], sh2[8], bcast[2];
    for (int o = 16; o; o >>= 1) {
        s  += __shfl_down_sync(0xffffffffu, s, o);
        ss += __shfl_down_sync(0xffffffffu, ss, o);
    }
    int lane = tid & 31, warp = tid >> 5;
    if (lane == 0) { sh1[warp] = s; sh2[warp] = ss; }
    __syncthreads();
    if (tid == 0) {
        s = 0.f; ss = 0.f;
        #pragma unroll
        for (int wv = 0; wv < 8; wv++) { s += sh1[wv]; ss += sh2[wv]; }
        float m = s / (float)Dq;
        float v = ss / (float)Dq - m*m;
        float r = rsqrtf(v + EPSq);
        bcast[0] = m; bcast[1] = r;
        rm[row] = m; rs[row] = r;
    }
    __syncthreads();
    float m = bcast[0], r = bcast[1];
    #pragma unroll
    for (int j = 0; j < 3; j++) {
        int c = tid + j*256;
        X1[(size_t)row*Dq + c] = vloc[j];
        XN[(size_t)row*Dq + c] = __float2half_rn((vloc[j] - m) * r * lng[c] + lnb[c]);
    }
}

// ---------------- combine + LN stats, fused ----------------
__global__ void __launch_bounds__(256) combine_ln(
    const float* __restrict__ X, const float* __restrict__ X1,
    const float* __restrict__ MO, const float* __restrict__ GL,
    const float* __restrict__ gb,
    float* __restrict__ XF, float* __restrict__ rm2, float* __restrict__ rs2)
{
    const int row = blockIdx.x;
    const int tid = threadIdx.x;
    float vloc[3];
    float s = 0.f, ss = 0.f;
    #pragma unroll
    for (int j = 0; j < 3; j++) {
        int c = tid + j*256;
        size_t i = (size_t)row*Dq + c;
        float gate = 1.f / (1.f + __expf(-(GL[i] + gb[c])));
        float v = X1[i] + MO[i]*gate + X[i];
        vloc[j] = v;
        s += v; ss += v*v;
    }
    __shared__ float sh1[8], sh2[8];
    for (int o = 16; o; o >>= 1) {
        s  += __shfl_down_sync(0xffffffffu, s, o);
        ss += __shfl_down_sync(0xffffffffu, ss, o);
    }
    int lane = tid & 31, warp = tid >> 5;
    if (lane == 0) { sh1[warp] = s; sh2[warp] = ss; }
    __syncthreads();
    if (tid == 0) {
        s = 0.f; ss = 0.f;
        #pragma unroll
        for (int wv = 0; wv < 8; wv++) { s += sh1[wv]; ss += sh2[wv]; }
        float m = s / (float)Dq;
        float v = ss / (float)Dq - m*m;
        rm2[row] = m;
        rs2[row] = rsqrtf(v + EPSq);
    }
    #pragma unroll
    for (int j = 0; j < 3; j++) {
        int c = tid + j*256;
        XF[(size_t)row*Dq + c] = vloc[j];
    }
}

// ---------------- causal conv K=4 + bias + silu -> fp16 ----------------
__global__ void conv_causal_silu(const float* __restrict__ XZ, const float* __restrict__ w,
                                 const float* __restrict__ bias, __half* __restrict__ Y)
{
    int idx = blockIdx.x * blockDim.x + threadIdx.x;
    if (idx >= Nq*DIq) return;
    int c  = idx % DIq;
    int l  = (idx / DIq) % Lq;
    int bb = idx / (DIq*Lq);
    float acc = bias[c];
    #pragma unroll
    for (int k = 0; k < 4; k++) {
        int ls = l - 3 + k;
        if (ls >= 0) acc += XZ[(size_t)(bb*Lq + ls)*(2*DIq) + c] * w[c*4 + k];
    }
    Y[idx] = __float2half_rn(acc / (1.f + __expf(-acc)));
}

// feat_attr
__global__ void attr_max(const float* __restrict__ X, const float* __restrict__ mean,
                         const float* __restrict__ rstd, const float* __restrict__ g,
                         const float* __restrict__ b, float* __restrict__ out)
{
    int c  = blockIdx.y * blockDim.x + threadIdx.x;
    int bb = blockIdx.x;
    float gm = g[c], gb = b[c];
    float mx = -3.4e38f;
    for (int l = 0; l < Lq; l++) {
        int row = bb*Lq + l;
        float v = (X[(size_t)row*Dq + c] - mean[row]) * rstd[row] * gm + gb;
        mx = fmaxf(mx, v);
    }
    out[bb*Dq + c] = mx;
}

// ---------------- selective scan (fp16 u, dbc, y) ----------------
__global__ void __launch_bounds__(128) scan_k(
    const float* __restrict__ delta, const __half* __restrict__ u,
    const __half* __restrict__ dbc,  const float* __restrict__ xz,
    const float* __restrict__ A_log, const float* __restrict__ Dp,
    __half* __restrict__ y)
{
    __shared__ float Bs[128][DSq];
    __shared__ float Cs[128][DSq];
    const int bb = blockIdx.y;
    const int d  = blockIdx.x * 128 + threadIdx.x;

    float A[DSq], h[DSq];
    bool fast = true;
    #pragma unroll
    for (int s = 0; s < DSq; s++) {
        A[s] = -expf(A_log[d*DSq + s]);
        h[s] = 0.f;
        if (fabsf(A[s] + (float)(s+1)) > 1e-3f * (float)(s+1)) fast = false;
    }
    const float dp = Dp[d];

    for (int c0 = 0; c0 < Lq; c0 += 128) {
        for (int i = threadIdx.x; i < 128*DSq; i += 128) {
            int l = i >> 4, s = i & 15;
            size_t row = (size_t)(bb*Lq + c0 + l);
            Bs[l][s] = __half2float(dbc[row*80 + DTRq + s]);
            Cs[l][s] = __half2float(dbc[row*80 + DTRq + DSq + s]);
        }
        __syncthreads();
        size_t row0 = (size_t)(bb*Lq + c0);
        float dv = delta[row0*DIq + d];
        float uv = __half2float(u[row0*DIq + d]);
        float zv = xz[row0*(2*DIq) + DIq + d];
        if (fast) {
            for (int l = 0; l < 128; l++) {
                float nd = 0.f, nu = 0.f, nz = 0.f;
                if (l < 127) {
                    size_t rn = row0 + l + 1;
                    nd = delta[rn*DIq + d];
                    nu = __half2float(u[rn*DIq + d]);
                    nz = xz[rn*(2*DIq) + DIq + d];
                }
                float du = dv * uv;
                float e1 = __expf(-dv);
                float p = e1;
                float acc = 0.f;
                #pragma unroll
                for (int s = 0; s < DSq; s++) {
                    h[s] = h[s] * p + du * Bs[l][s];
                    acc  = fmaf(h[s], Cs[l][s], acc);
                    p *= e1;
                }
                float sz = zv / (1.f + __expf(-zv));
                y[(row0 + l)*DIq + d] = __float2half_rn((acc + uv*dp) * sz);
                dv = nd; uv = nu; zv = nz;
            }
        } else {
            for (int l = 0; l < 128; l++) {
                float nd = 0.f, nu = 0.f, nz = 0.f;
                if (l < 127) {
                    size_t rn = row0 + l + 1;
                    nd = delta[rn*DIq + d];
                    nu = __half2float(u[rn*DIq + d]);
                    nz = xz[rn*(2*DIq) + DIq + d];
                }
                float du = dv * uv;
                float acc = 0.f;
                #pragma unroll
                for (int s = 0; s < DSq; s++) {
                    h[s] = h[s] * __expf(dv * A[s]) + du * Bs[l][s];
                    acc  = fmaf(h[s], Cs[l][s], acc);
                }
                float sz = zv / (1.f + __expf(-zv));
                y[(row0 + l)*DIq + d] = __float2half_rn((acc + uv*dp) * sz);
                dv = nd; uv = nu; zv = nz;
            }
        }
        __syncthreads();
    }
}

// feat_id
__global__ void feat_id_k(const float* __restrict__ X, const float* __restrict__ mean,
                          const float* __restrict__ rstd, const float* __restrict__ g,
                          const float* __restrict__ b, float* __restrict__ fid,
                          float* __restrict__ out)
{
    int c  = blockIdx.y * blockDim.x + threadIdx.x;
    int bb = blockIdx.x;
    float gm = g[c], gb = b[c];
    float s = 0.f;
    for (int l = 0; l < Lq; l++) {
        int row = bb*Lq + l;
        s += (X[(size_t)row*Dq + c] - mean[row]) * rstd[row] * gm + gb;
    }
    float v = s / (float)Lq;
    fid[bb*Dq + c] = v;
    out[bb*Dq + c] = v;
}

__global__ void feat_bn(const float* __restrict__ fid, const float* __restrict__ g,
                        const float* __restrict__ b, float* __restrict__ out)
{
    int c = blockIdx.x * blockDim.x + threadIdx.x;
    if (c >= Dq) return;
    float s = 0.f, ss = 0.f;
    for (int bb = 0; bb < Bq; bb++) {
        float v = fid[bb*Dq + c]; s += v; ss += v*v;
    }
    float m = s / (float)Bq;
    float var = ss / (float)Bq - m*m;
    float rs = rsqrtf(var + EPSq);
    for (int bb = 0; bb < Bq; bb++)
        out[bb*Dq + c] = (fid[bb*Dq + c] - m) * rs * g[c] + b[c];
}

// ---------------- host ----------------
#define GETSYMT(p, s, T) { void* _t; cudaGetSymbolAddress(&_t, s); p = (T*)_t; }

extern "C" void kernel_launch(void* const* d_in, const int* in_sizes, int n_in,
                              void* d_out, int out_size)
{
    const float* x        = (const float*)d_in[0];
    const float* sq_w     = (const float*)d_in[1];
    const float* sq_bn_g  = (const float*)d_in[2];
    const float* sq_bn_b  = (const float*)d_in[3];
    const float* dw_w     = (const float*)d_in[4];
    const float* dw_bn_g  = (const float*)d_in[5];
    const float* dw_bn_b  = (const float*)d_in[6];
    const float* ex_w     = (const float*)d_in[7];
    const float* ex_bn_g  = (const float*)d_in[8];
    const float* ex_bn_b  = (const float*)d_in[9];
    const float* attr_g   = (const float*)d_in[10];
    const float* attr_b   = (const float*)d_in[11];
    const float* mnorm_g  = (const float*)d_in[12];
    const float* mnorm_b  = (const float*)d_in[13];
    const float* in_proj_w= (const float*)d_in[14];
    const float* conv_w   = (const float*)d_in[15];
    const float* conv_b   = (const float*)d_in[16];
    const float* xproj_w  = (const float*)d_in[17];
    const float* dtproj_w = (const float*)d_in[18];
    const float* dtproj_b = (const float*)d_in[19];
    const float* A_log    = (const float*)d_in[20];
    const float* D_param  = (const float*)d_in[21];
    const float* out_proj_w = (const float*)d_in[22];
    const float* gate_w   = (const float*)d_in[23];
    const float* gate_b   = (const float*)d_in[24];
    const float* idn_g    = (const float*)d_in[25];
    const float* idn_b    = (const float*)d_in[26];
    const float* idbn_g   = (const float*)d_in[27];
    const float* idbn_b   = (const float*)d_in[28];
    float* out = (float*)d_out;

    float *h0,*tmpH,*e,*x1,*xz,*del,*mo,*gl,*xf,*rm,*rs,*rm2,*rs2,*fid,*stats;
    __half *h2,*xn,*xm2,*dbc,*y,*xr,*wh;
    GETSYMT(h0, g_h0, float);   GETSYMT(tmpH, g_tmpH, float);
    GETSYMT(h2, g_h2, __half);  GETSYMT(e, g_e, float);
    GETSYMT(x1, g_x1, float);   GETSYMT(xn, g_xn, __half);
    GETSYMT(xz, g_xz, float);   GETSYMT(xm2, g_xm2, __half);
    GETSYMT(dbc, g_dbc, __half);GETSYMT(del, g_del, float);
    GETSYMT(y, g_y, __half);    GETSYMT(mo, g_mo, float);
    GETSYMT(gl, g_gl, float);   GETSYMT(xf, g_xf, float);
    GETSYMT(rm, g_rm, float);   GETSYMT(rs, g_rs, float);
    GETSYMT(rm2, g_rm2, float); GETSYMT(rs2, g_rs2, float);
    GETSYMT(fid, g_fid, float); GETSYMT(stats, g_stats, float);
    GETSYMT(xr, g_xr, __half);  GETSYMT(wh, g_wh, __half);

    float* sum1 = stats + ST_SUM1;
    float* sq1  = stats + ST_SQ1;
    float* sum2 = stats + ST_SUM2;
    float* sq2  = stats + ST_SQ2;
    float* sum3 = stats + ST_SUM3;
    float* sq3  = stats + ST_SQ3;

    static cudaStream_t s1 = 0;
    static cudaEvent_t evW0 = 0, evWdone = 0, evFork = 0, evZ = 0, evJoin = 0;
    static int smemSet = 0;
    if (!s1) {
        cudaStreamCreateWithFlags(&s1, cudaStreamNonBlocking);
        cudaEventCreateWithFlags(&evW0, cudaEventDisableTiming);
        cudaEventCreateWithFlags(&evWdone, cudaEventDisableTiming);
        cudaEventCreateWithFlags(&evFork, cudaEventDisableTiming);
        cudaEventCreateWithFlags(&evZ, cudaEventDisableTiming);
        cudaEventCreateWithFlags(&evJoin, cudaEventDisableTiming);
    }
    if (!smemSet) {
        cudaFuncSetAttribute(gemm_tc<0>, cudaFuncAttributeMaxDynamicSharedMemorySize, GEMM_DSMEM);
        cudaFuncSetAttribute(gemm_tc<1>, cudaFuncAttributeMaxDynamicSharedMemorySize, GEMM_DSMEM);
        cudaFuncSetAttribute(gemm_tc<2>, cudaFuncAttributeMaxDynamicSharedMemorySize, GEMM_DSMEM);
        smemSet = 1;
    }

    const int T = 256;
    dim3 gHID((Nq*HIDq + T-1)/T), gDI((Nq*DIq + T-1)/T);

    cudaMemsetAsync(stats, 0, ST_TOTAL*sizeof(float));

    // 0) converts needed now (main): x, sq_w, ex_w
    cvt_f16<<<(Nq*Dq/4 + 255)/256, 256>>>(x, xr, Nq*Dq/4);
    cvt_f16<<<(HIDq*Dq/4 + 255)/256, 256>>>(sq_w, wh + W_SQ, HIDq*Dq/4);
    cvt_f16<<<(Dq*HIDq/4 + 255)/256, 256>>>(ex_w, wh + W_EX, Dq*HIDq/4);
    // later-needed converts on side stream (hidden under squeeze/BN phase)
    cudaEventRecord(evW0, 0);
    cudaStreamWaitEvent(s1, evW0, 0);
    cvt_f16<<<(2*DIq*Dq/4 + 255)/256, 256, 0, s1>>>(in_proj_w, wh + W_INP, 2*DIq*Dq/4);
    cvt_f16<<<(80*DIq/4 + 255)/256, 256, 0, s1>>>(xproj_w,  wh + W_XP,  80*DIq/4);
    cvt_f16<<<(DIq*DTRq/4 + 255)/256, 256, 0, s1>>>(dtproj_w, wh + W_DT, DIq*DTRq/4);
    cvt_f16<<<(Dq*DIq/4 + 255)/256, 256, 0, s1>>>(out_proj_w, wh + W_OUT, Dq*DIq/4);
    cvt_f16<<<(Dq*Dq/4 + 255)/256, 256, 0, s1>>>(gate_w, wh + W_GATE, Dq*Dq/4);
    cudaEventRecord(evWdone, s1);

    // 1) squeeze GEMM + BN+SiLU
    gemm_tc<0><<<dim3(2, Nq/128), 256, GEMM_DSMEM>>>(xr, Dq, wh + W_SQ, h0, HIDq, HIDq, Dq, 0);
    bn_stats<<<dim3(256,1), T>>>(h0, Nq, HIDq, sum1, sq1);
    bn_silu<false><<<gHID, T>>>(h0, h0, sum1, sq1, sq_bn_g, sq_bn_b, Nq, HIDq);

    // 2) dwconv K=5 + BN+SiLU (h2 fp16)
    dwconv5<<<gHID, T>>>(h0, dw_w, tmpH);
    bn_stats<<<dim3(256,1), T>>>(tmpH, Nq, HIDq, sum2, sq2);
    bn_silu<true><<<gHID, T>>>(tmpH, h2, sum2, sq2, dw_bn_g, dw_bn_b, Nq, HIDq);

    // 3) excite GEMM + fused bn_add + LN (xn fp16)
    gemm_tc<0><<<dim3(6, Nq/128), 256, GEMM_DSMEM>>>(h2, HIDq, wh + W_EX, e, Dq, Dq, HIDq, 0);
    bn_stats<<<dim3(256,3), T>>>(e, Nq, Dq, sum3, sq3);
    bn_add_ln<<<Nq, T>>>(e, x, sum3, sq3, ex_bn_g, ex_bn_b, mnorm_g, mnorm_b,
                         x1, xn, rm, rs);

    // fork: side stream z-half of in_proj, feat_attr, gate GEMM
    cudaEventRecord(evFork, 0);
    cudaStreamWaitEvent(s1, evFork, 0);
    gemm_tc<0><<<dim3(12, Nq/128), 256, GEMM_DSMEM, s1>>>(
        xn, Dq, wh + W_INP + (size_t)DIq*Dq, xz + DIq, DIq, 2*DIq, Dq, 0);
    cudaEventRecord(evZ, s1);
    attr_max<<<dim3(Bq,3), T, 0, s1>>>(x1, rm, rs, attr_g, attr_b, out);
    gemm_tc<0><<<dim3(6, Nq/128), 256, GEMM_DSMEM, s1>>>(xn, Dq, wh + W_GATE, gl, Dq, Dq, Dq, 0);
    cudaEventRecord(evJoin, s1);

    // 5) main: xm-half of in_proj (needs converted weights)
    cudaStreamWaitEvent(0, evWdone, 0);
    gemm_tc<0><<<dim3(12, Nq/128), 256, GEMM_DSMEM>>>(
        xn, Dq, wh + W_INP, xz, DIq, 2*DIq, Dq, 0);

    // 6) causal conv + silu -> xm2 fp16
    conv_causal_silu<<<gDI, T>>>(xz, conv_w, conv_b, xm2);

    // 7) x_proj (fp16 out); dt_proj (+softplus, float out)
    gemm_tc<2><<<dim3(1, Nq/128), 256, GEMM_DSMEM>>>(xm2, DIq, wh + W_XP, (float*)dbc, 80, 80, DIq, 0);
    gemm_tc<1><<<dim3(12, Nq/128), 256, GEMM_DSMEM>>>(dbc, 80, wh + W_DT, del, DIq, DIq, DTRq, dtproj_b);

    // 8) selective scan (needs z-half)
    cudaStreamWaitEvent(0, evZ, 0);
    scan_k<<<dim3(DIq/128, Bq), 128>>>(del, xm2, dbc, xz, A_log, D_param, y);

    // 9) out_proj; join gate; fused combine + LN stats
    gemm_tc<0><<<dim3(6, Nq/128), 256, GEMM_DSMEM>>>(y, DIq, wh + W_OUT, mo, Dq, Dq, DIq, 0);
    cudaStreamWaitEvent(0, evJoin, 0);
    combine_ln<<<Nq, T>>>(x, x1, mo, gl, gate_b, xf, rm2, rs2);

    // 10) feat_id + feat_id_bn
    feat_id_k<<<dim3(Bq,3), T>>>(xf, rm2, rs2, idn_g, idn_b, fid, out + Bq*Dq);
    feat_bn<<<3, T>>>(fid, idbn_g, idbn_b, out + 2*Bq*Dq);
}

// round 12
// speedup vs baseline: 1.0795x; 1.0795x over previous
#include <cuda_runtime.h>
#include <math.h>
#include <stdint.h>

#define Bq    32
#define Lq    512
#define Dq    768
#define HIDq  192
#define DIq   1536
#define DSq   16
#define DTRq  48
#define Nq    (Bq*Lq)        // 16384
#define EPSq  1e-5f

// ---------------- scratch ----------------
__device__ __align__(256) float g_h0  [Nq*HIDq];
__device__ __align__(256) float g_tmpH[Nq*HIDq];
__device__ __align__(256) float g_h2  [Nq*HIDq];
__device__ __align__(256) float g_e   [Nq*Dq];
__device__ __align__(256) float g_x1  [Nq*Dq];
__device__ __align__(256) float g_xn  [Nq*Dq];
__device__ __align__(256) float g_xz  [Nq*2*DIq];
__device__ __align__(256) float g_xm2 [Nq*DIq];
__device__ __align__(256) float g_dbc [Nq*80];
__device__ __align__(256) float g_del [Nq*DIq];
__device__ __align__(256) float g_y   [Nq*DIq];
__device__ __align__(256) float g_mo  [Nq*Dq];
__device__ __align__(256) float g_gl  [Nq*Dq];
__device__ __align__(256) float g_xf  [Nq*Dq];
__device__ __align__(256) float g_rm  [Nq];
__device__ __align__(256) float g_rs  [Nq];
__device__ __align__(256) float g_rm2 [Nq];
__device__ __align__(256) float g_rs2 [Nq];
__device__ __align__(256) float g_fid [Bq*Dq];
__device__ __align__(256) float g_xr  [Nq*Dq];     // tf32-rounded x
// tf32-rounded weights, concatenated
#define W_SQ   0
#define W_EX   (W_SQ  + HIDq*Dq)
#define W_INP  (W_EX  + Dq*HIDq)
#define W_XP   (W_INP + 2*DIq*Dq)
#define W_DT   (W_XP  + 80*DIq)
#define W_OUT  (W_DT  + DIq*DTRq)
#define W_GATE (W_OUT + Dq*DIq)
#define W_TOT  (W_GATE + Dq*Dq)
__device__ __align__(256) float g_wr[W_TOT];
#define ST_SUM1   0
#define ST_SQ1    (ST_SUM1+192)
#define ST_SUM2   (ST_SQ1+192)
#define ST_SQ2    (ST_SUM2+192)
#define ST_SUM3   (ST_SQ2+192)
#define ST_SQ3    (ST_SUM3+768)
#define ST_TOTAL  (ST_SQ3+768)
__device__ __align__(256) float g_stats[ST_TOTAL];

// ================= helpers =================
__device__ __forceinline__ uint32_t f2tf(float f) {
    uint32_t u;
    asm("cvt.rna.tf32.f32 %0, %1;" : "=r"(u) : "f"(f));
    return u;
}
__device__ __forceinline__ float f2tf_f(float f) { return __uint_as_float(f2tf(f)); }

__device__ __forceinline__ void mma_tf32(float* d, const uint32_t* a, const uint32_t* b) {
    asm volatile(
        "mma.sync.aligned.m16n8k8.row.col.f32.tf32.tf32.f32 "
        "{%0,%1,%2,%3}, {%4,%5,%6,%7}, {%8,%9}, {%0,%1,%2,%3};"
        : "+f"(d[0]), "+f"(d[1]), "+f"(d[2]), "+f"(d[3])
        : "r"(a[0]), "r"(a[1]), "r"(a[2]), "r"(a[3]), "r"(b[0]), "r"(b[1]));
}

__device__ __forceinline__ uint32_t smem_u32(const void* p) {
    uint32_t a;
    asm("{ .reg .u64 t; cvta.to.shared.u64 t, %1; cvt.u32.u64 %0, t; }" : "=r"(a) : "l"(p));
    return a;
}
#define CP_ASYNC(dst, src, sz) \
    asm volatile("cp.async.cg.shared.global [%0], [%1], 16, %2;" \
                 :: "r"(dst), "l"(src), "r"(sz) : "memory")
#define CP_COMMIT() asm volatile("cp.async.commit_group;" ::: "memory")
#define CP_WAIT(n)  asm volatile("cp.async.wait_group %0;" :: "n"(n) : "memory")

// ================= TF32 GEMM: cp.async staged, 2 CTAs/SM =================
// C[M,Nc] = A[M,K](lda) @ W[Nc,K]^T, C row stride ldc. Inputs PRE-ROUNDED to tf32.
// MODE 0: plain store. MODE 1: softplus(v+p0[c]). MODE 2: tf32-rounded store.
// MODE 3: plain store + per-channel sum/sq atomics into psum/psq.
#define SA 36
#define TILE_U (128*SA)
#define GEMM_DSMEM (2*2*TILE_U*4)

template<int MODE>
__global__ void __launch_bounds__(256, 2) gemm_tc(
    const float* __restrict__ A, int lda,
    const float* __restrict__ W,
    float* __restrict__ C, int Nc, int ldc, int K,
    const float* __restrict__ p0,
    float* __restrict__ psum, float* __restrict__ psq)
{
    extern __shared__ uint32_t dsm[];
    const uint32_t sbase = smem_u32(dsm);

    const int bm = blockIdx.y * 128;
    const int bn = blockIdx.x * 128;
    const int t  = threadIdx.x;
    const int wid  = t >> 5;
    const int lane = t & 31;
    const int qr = lane >> 2;
    const int qc = lane & 3;
    const int warp_m = wid & 3;
    const int warp_n = wid >> 2;

    const int r0t = t >> 3;            // 0..31
    const int c4  = (t & 7) * 4;       // 0..28

    const float* aRow[4];
    const float* bRow[4];
    int bOk[4];
    uint32_t dstOff[4];
    #pragma unroll
    for (int i = 0; i < 4; i++) {
        int r = r0t + i*32;
        aRow[i] = A + (size_t)(bm + r)*lda;
        int j = bn + r;
        bOk[i] = (j < Nc);
        bRow[i] = W + (size_t)(bOk[i] ? j : 0)*K;
        dstOff[i] = (uint32_t)(r*SA + c4) * 4u;
    }

    float acc[2][8][4];
    #pragma unroll
    for (int mt = 0; mt < 2; mt++)
        #pragma unroll
        for (int nt = 0; nt < 8; nt++)
            #pragma unroll
            for (int q = 0; q < 4; q++) acc[mt][nt][q] = 0.f;

    const int NC = (K + 31) / 32;

    // prologue: chunk 0 -> stage 0
    {
        int k = c4;
        int szA = (k < K) ? 16 : 0;
        #pragma unroll
        for (int i = 0; i < 4; i++)
            CP_ASYNC(sbase + dstOff[i], aRow[i] + k, szA);
        #pragma unroll
        for (int i = 0; i < 4; i++) {
            int szB = (bOk[i] && k < K) ? 16 : 0;
            CP_ASYNC(sbase + (uint32_t)TILE_U*4 + dstOff[i], bRow[i] + k, szB);
        }
        CP_COMMIT();
    }

    for (int ch = 0; ch < NC; ch++) {
        const int buf = ch & 1;
        if (ch + 1 < NC) {
            const int k = (ch + 1)*32 + c4;
            uint32_t base = sbase + (uint32_t)(buf ^ 1) * 2u * TILE_U * 4u;
            int szA = (k < K) ? 16 : 0;
            #pragma unroll
            for (int i = 0; i < 4; i++)
                CP_ASYNC(base + dstOff[i], aRow[i] + k, szA);
            #pragma unroll
            for (int i = 0; i < 4; i++) {
                int szB = (bOk[i] && k < K) ? 16 : 0;
                CP_ASYNC(base + (uint32_t)TILE_U*4 + dstOff[i], bRow[i] + k, szB);
            }
            CP_COMMIT();
            CP_WAIT(1);
        } else {
            CP_WAIT(0);
        }
        __syncthreads();

        const uint32_t* As = dsm + (size_t)buf * 2 * TILE_U;
        const uint32_t* Bs = As + TILE_U;
        #pragma unroll
        for (int ks = 0; ks < 4; ks++) {
            const int k0 = ks * 8;
            uint32_t afr[2][4];
            #pragma unroll
            for (int mt = 0; mt < 2; mt++) {
                int r0 = warp_m*32 + mt*16 + qr;
                afr[mt][0] = As[r0*SA + k0 + qc];
                afr[mt][1] = As[(r0+8)*SA + k0 + qc];
                afr[mt][2] = As[r0*SA + k0 + qc + 4];
                afr[mt][3] = As[(r0+8)*SA + k0 + qc + 4];
            }
            uint32_t bfr[8][2];
            #pragma unroll
            for (int nt = 0; nt < 8; nt++) {
                int n = warp_n*64 + nt*8 + qr;
                bfr[nt][0] = Bs[n*SA + k0 + qc];
                bfr[nt][1] = Bs[n*SA + k0 + qc + 4];
            }
            #pragma unroll
            for (int mt = 0; mt < 2; mt++)
                #pragma unroll
                for (int nt = 0; nt < 8; nt++)
                    mma_tf32(acc[mt][nt], afr[mt], bfr[nt]);
        }
        __syncthreads();
    }

    if (MODE == 0 || MODE == 2) {
        #pragma unroll
        for (int mt = 0; mt < 2; mt++) {
            int r0 = bm + warp_m*32 + mt*16 + qr;
            #pragma unroll
            for (int nt = 0; nt < 8; nt++) {
                int c = bn + warp_n*64 + nt*8 + qc*2;
                if (c < Nc) {
                    float v0 = acc[mt][nt][0], v1 = acc[mt][nt][1];
                    float v2 = acc[mt][nt][2], v3 = acc[mt][nt][3];
                    if (MODE == 2) { v0 = f2tf_f(v0); v1 = f2tf_f(v1); v2 = f2tf_f(v2); v3 = f2tf_f(v3); }
                    *(float2*)&C[(size_t)r0*ldc + c]     = make_float2(v0, v1);
                    *(float2*)&C[(size_t)(r0+8)*ldc + c] = make_float2(v2, v3);
                }
            }
        }
    } else if (MODE == 1) {
        #pragma unroll
        for (int mt = 0; mt < 2; mt++) {
            int r0 = bm + warp_m*32 + mt*16 + qr;
            #pragma unroll
            for (int nt = 0; nt < 8; nt++) {
                int c = bn + warp_n*64 + nt*8 + qc*2;
                if (c < Nc) {
                    float b0 = p0[c], b1 = p0[c+1];
                    float v;
                    v = acc[mt][nt][0] + b0; v = (v > 20.f) ? v : log1pf(__expf(v));
                    C[(size_t)r0*ldc + c] = v;
                    v = acc[mt][nt][1] + b1; v = (v > 20.f) ? v : log1pf(__expf(v));
                    C[(size_t)r0*ldc + c + 1] = v;
                    v = acc[mt][nt][2] + b0; v = (v > 20.f) ? v : log1pf(__expf(v));
                    C[(size_t)(r0+8)*ldc + c] = v;
                    v = acc[mt][nt][3] + b1; v = (v > 20.f) ? v : log1pf(__expf(v));
                    C[(size_t)(r0+8)*ldc + c + 1] = v;
                }
            }
        }
    } else {
        // MODE 3: store + per-channel stats (sum over this CTA's 128 rows)
        float s[16], ss[16];
        #pragma unroll
        for (int i = 0; i < 16; i++) { s[i] = 0.f; ss[i] = 0.f; }
        #pragma unroll
        for (int mt = 0; mt < 2; mt++) {
            int r0 = bm + warp_m*32 + mt*16 + qr;
            #pragma unroll
            for (int nt = 0; nt < 8; nt++) {
                int c = bn + warp_n*64 + nt*8 + qc*2;
                if (c < Nc) {
                    *(float2*)&C[(size_t)r0*ldc + c]     = make_float2(acc[mt][nt][0], acc[mt][nt][1]);
                    *(float2*)&C[(size_t)(r0+8)*ldc + c] = make_float2(acc[mt][nt][2], acc[mt][nt][3]);
                    #pragma unroll
                    for (int h = 0; h < 2; h++) {
                        float v0 = acc[mt][nt][h], v1 = acc[mt][nt][h+2];
                        s[nt*2+h]  += v0 + v1;
                        ss[nt*2+h] += v0*v0 + v1*v1;
                    }
                }
            }
        }
        // reduce over qr (lanes with same qc: stride 4)
        #pragma unroll
        for (int o = 4; o < 32; o <<= 1) {
            #pragma unroll
            for (int i = 0; i < 16; i++) {
                s[i]  += __shfl_xor_sync(0xffffffffu, s[i], o);
                ss[i] += __shfl_xor_sync(0xffffffffu, ss[i], o);
            }
        }
        if (qr == 0) {
            #pragma unroll
            for (int nt = 0; nt < 8; nt++)
                #pragma unroll
                for (int h = 0; h < 2; h++) {
                    int c = bn + warp_n*64 + nt*8 + qc*2 + h;
                    if (c < Nc) {
                        atomicAdd(&psum[c], s[nt*2+h]);
                        atomicAdd(&psq[c],  ss[nt*2+h]);
                    }
                }
        }
    }
}

// ---------------- tf32 pre-round ----------------
__global__ void round_tf32(const float* __restrict__ X, float* __restrict__ Y, int n4)
{
    int i = blockIdx.x * blockDim.x + threadIdx.x;
    if (i >= n4) return;
    float4 v = ((const float4*)X)[i];
    v.x = f2tf_f(v.x); v.y = f2tf_f(v.y); v.z = f2tf_f(v.z); v.w = f2tf_f(v.w);
    ((float4*)Y)[i] = v;
}

// ---------------- BatchNorm stats ----------------
__global__ void bn_stats(const float* __restrict__ X, int M, int C,
                         float* __restrict__ sum, float* __restrict__ sq)
{
    int c = blockIdx.y * blockDim.x + threadIdx.x;
    if (c >= C) return;
    int rows = M / gridDim.x;
    int r0 = blockIdx.x * rows;
    float s = 0.f, ss = 0.f;
    for (int r = r0; r < r0 + rows; r++) {
        float v = X[(size_t)r*C + c];
        s += v; ss += v*v;
    }
    atomicAdd(&sum[c], s);
    atomicAdd(&sq[c],  ss);
}

__global__ void bn_silu(const float* __restrict__ X, float* __restrict__ Y,
                        const float* __restrict__ sum, const float* __restrict__ sq,
                        const float* __restrict__ g, const float* __restrict__ b,
                        int M, int C)
{
    int idx = blockIdx.x * blockDim.x + threadIdx.x;
    if (idx >= M*C) return;
    int c = idx % C;
    float mean = sum[c] / (float)M;
    float var  = sq[c] / (float)M - mean*mean;
    float v = (X[idx] - mean) * rsqrtf(var + EPSq) * g[c] + b[c];
    Y[idx] = f2tf_f(v / (1.f + __expf(-v)));
}

// ---------------- depthwise conv K=5 ----------------
__global__ void dwconv5(const float* __restrict__ X, const float* __restrict__ w,
                        float* __restrict__ Y)
{
    int idx = blockIdx.x * blockDim.x + threadIdx.x;
    if (idx >= Nq*HIDq) return;
    int c  = idx % HIDq;
    int l  = (idx / HIDq) % Lq;
    int bb = idx / (HIDq*Lq);
    const float* xb = X + (size_t)bb*Lq*HIDq;
    float acc = 0.f;
    #pragma unroll
    for (int k = 0; k < 5; k++) {
        int ls = l - 2 + k;
        if (ls >= 0 && ls < Lq) acc += xb[(size_t)ls*HIDq + c] * w[c*5 + k];
    }
    Y[idx] = acc;
}

// ---------------- bn_add + LN, fused (xn tf32-rounded) ----------------
__global__ void __launch_bounds__(256) bn_add_ln(
    const float* __restrict__ E, const float* __restrict__ X,
    const float* __restrict__ sum3, const float* __restrict__ sq3,
    const float* __restrict__ exg, const float* __restrict__ exb,
    const float* __restrict__ lng, const float* __restrict__ lnb,
    float* __restrict__ X1, float* __restrict__ XN,
    float* __restrict__ rm, float* __restrict__ rs)
{
    const int row = blockIdx.x;
    const int tid = threadIdx.x;
    float vloc[3];
    float s = 0.f, ss = 0.f;
    #pragma unroll
    for (int j = 0; j < 3; j++) {
        int c = tid + j*256;
        float mean = sum3[c] / (float)Nq;
        float var  = sq3[c] / (float)Nq - mean*mean;
        float ga = rsqrtf(var + EPSq) * exg[c];
        float be = exb[c] - mean*ga;
        float v = X[(size_t)row*Dq + c] + E[(size_t)row*Dq + c]*ga + be;
        vloc[j] = v;
        s += v; ss += v*v;
    }
    __shared__ float sh1[8], sh2[8], bcast[2];
    for (int o = 16; o; o >>= 1) {
        s  += __shfl_down_sync(0xffffffffu, s, o);
        ss += __shfl_down_sync(0xffffffffu, ss, o);
    }
    int lane = tid & 31, warp = tid >> 5;
    if (lane == 0) { sh1[warp] = s; sh2[warp] = ss; }
    __syncthreads();
    if (tid == 0) {
        s = 0.f; ss = 0.f;
        #pragma unroll
        for (int wv = 0; wv < 8; wv++) { s += sh1[wv]; ss += sh2[wv]; }
        float m = s / (float)Dq;
        float v = ss / (float)Dq - m*m;
        float r = rsqrtf(v + EPSq);
        bcast[0] = m; bcast[1] = r;
        rm[row] = m; rs[row] = r;
    }
    __syncthreads();
    float m = bcast[0], r = bcast[1];
    #pragma unroll
    for (int j = 0; j < 3; j++) {
        int c = tid + j*256;
        X1[(size_t)row*Dq + c] = vloc[j];
        XN[(size_t)row*Dq + c] = f2tf_f((vloc[j] - m) * r * lng[c] + lnb[c]);
    }
}

// ---------------- combine + LN stats, fused ----------------
__global__ void __launch_bounds__(256) combine_ln(
    const float* __restrict__ X, const float* __restrict__ X1,
    const float* __restrict__ MO, const float* __restrict__ GL,
    const float* __restrict__ gb,
    float* __restrict__ XF, float* __restrict__ rm2, float* __restrict__ rs2)
{
    const int row = blockIdx.x;
    const int tid = threadIdx.x;
    float vloc[3];
    float s = 0.f, ss = 0.f;
    #pragma unroll
    for (int j = 0; j < 3; j++) {
        int c = tid + j*256;
        size_t i = (size_t)row*Dq + c;
        float gate = 1.f / (1.f + __expf(-(GL[i] + gb[c])));
        float v = X1[i] + MO[i]*gate + X[i];
        vloc[j] = v;
        s += v; ss += v*v;
    }
    __shared__ float sh1[8], sh2[8];
    for (int o = 16; o; o >>= 1) {
        s  += __shfl_down_sync(0xffffffffu, s, o);
        ss += __shfl_down_sync(0xffffffffu, ss, o);
    }
    int lane = tid & 31, warp = tid >> 5;
    if (lane == 0) { sh1[warp] = s; sh2[warp] = ss; }
    __syncthreads();
    if (tid == 0) {
        s = 0.f; ss = 0.f;
        #pragma unroll
        for (int wv = 0; wv < 8; wv++) { s += sh1[wv]; ss += sh2[wv]; }
        float m = s / (float)Dq;
        float v = ss / (float)Dq - m*m;
        rm2[row] = m;
        rs2[row] = rsqrtf(v + EPSq);
    }
    #pragma unroll
    for (int j = 0; j < 3; j++) {
        int c = tid + j*256;
        XF[(size_t)row*Dq + c] = vloc[j];
    }
}

// ---------------- causal conv K=4 + bias + silu (tf32-rounded out) ----------------
__global__ void conv_causal_silu(const float* __restrict__ XZ, const float* __restrict__ w,
                                 const float* __restrict__ bias, float* __restrict__ Y)
{
    int idx = blockIdx.x * blockDim.x + threadIdx.x;
    if (idx >= Nq*DIq) return;
    int c  = idx % DIq;
    int l  = (idx / DIq) % Lq;
    int bb = idx / (DIq*Lq);
    float acc = bias[c];
    #pragma unroll
    for (int k = 0; k < 4; k++) {
        int ls = l - 3 + k;
        if (ls >= 0) acc += XZ[(size_t)(bb*Lq + ls)*(2*DIq) + c] * w[c*4 + k];
    }
    Y[idx] = f2tf_f(acc / (1.f + __expf(-acc)));
}

// feat_attr
__global__ void attr_max(const float* __restrict__ X, const float* __restrict__ mean,
                         const float* __restrict__ rstd, const float* __restrict__ g,
                         const float* __restrict__ b, float* __restrict__ out)
{
    int c  = blockIdx.y * blockDim.x + threadIdx.x;
    int bb = blockIdx.x;
    float gm = g[c], gb = b[c];
    float mx = -3.4e38f;
    for (int l = 0; l < Lq; l++) {
        int row = bb*Lq + l;
        float v = (X[(size_t)row*Dq + c] - mean[row]) * rstd[row] * gm + gb;
        mx = fmaxf(mx, v);
    }
    out[bb*Dq + c] = mx;
}

// ---------------- selective scan (pow-chain fast path; y tf32-rounded) ----------------
__global__ void __launch_bounds__(128) scan_k(
    const float* __restrict__ delta, const float* __restrict__ u,
    const float* __restrict__ dbc,   const float* __restrict__ xz,
    const float* __restrict__ A_log, const float* __restrict__ Dp,
    float* __restrict__ y)
{
    __shared__ float Bs[128][DSq];
    __shared__ float Cs[128][DSq];
    const int bb = blockIdx.y;
    const int d  = blockIdx.x * 128 + threadIdx.x;

    float A[DSq], h[DSq];
    bool fast = true;
    #pragma unroll
    for (int s = 0; s < DSq; s++) {
        A[s] = -expf(A_log[d*DSq + s]);
        h[s] = 0.f;
        if (fabsf(A[s] + (float)(s+1)) > 1e-3f * (float)(s+1)) fast = false;
    }
    const float dp = Dp[d];

    for (int c0 = 0; c0 < Lq; c0 += 128) {
        for (int i = threadIdx.x; i < 128*DSq; i += 128) {
            int l = i >> 4, s = i & 15;
            size_t row = (size_t)(bb*Lq + c0 + l);
            Bs[l][s] = dbc[row*80 + DTRq + s];
            Cs[l][s] = dbc[row*80 + DTRq + DSq + s];
        }
        __syncthreads();
        size_t row0 = (size_t)(bb*Lq + c0);
        float dv = delta[row0*DIq + d];
        float uv = u[row0*DIq + d];
        float zv = xz[row0*(2*DIq) + DIq + d];
        if (fast) {
            for (int l = 0; l < 128; l++) {
                float nd = 0.f, nu = 0.f, nz = 0.f;
                if (l < 127) {
                    size_t rn = row0 + l + 1;
                    nd = delta[rn*DIq + d];
                    nu = u[rn*DIq + d];
                    nz = xz[rn*(2*DIq) + DIq + d];
                }
                float du = dv * uv;
                float e1 = __expf(-dv);
                float p = e1;
                float acc = 0.f;
                #pragma unroll
                for (int s = 0; s < DSq; s++) {
                    h[s] = h[s] * p + du * Bs[l][s];
                    acc  = fmaf(h[s], Cs[l][s], acc);
                    p *= e1;
                }
                float sz = zv / (1.f + __expf(-zv));
                y[(row0 + l)*DIq + d] = f2tf_f((acc + uv*dp) * sz);
                dv = nd; uv = nu; zv = nz;
            }
        } else {
            for (int l = 0; l < 128; l++) {
                float nd = 0.f, nu = 0.f, nz = 0.f;
                if (l < 127) {
                    size_t rn = row0 + l + 1;
                    nd = delta[rn*DIq + d];
                    nu = u[rn*DIq + d];
                    nz = xz[rn*(2*DIq) + DIq + d];
                }
                float du = dv * uv;
                float acc = 0.f;
                #pragma unroll
                for (int s = 0; s < DSq; s++) {
                    h[s] = h[s] * __expf(dv * A[s]) + du * Bs[l][s];
                    acc  = fmaf(h[s], Cs[l][s], acc);
                }
                float sz = zv / (1.f + __expf(-zv));
                y[(row0 + l)*DIq + d] = f2tf_f((acc + uv*dp) * sz);
                dv = nd; uv = nu; zv = nz;
            }
        }
        __syncthreads();
    }
}

// feat_id
__global__ void feat_id_k(const float* __restrict__ X, const float* __restrict__ mean,
                          const float* __restrict__ rstd, const float* __restrict__ g,
                          const float* __restrict__ b, float* __restrict__ fid,
                          float* __restrict__ out)
{
    int c  = blockIdx.y * blockDim.x + threadIdx.x;
    int bb = blockIdx.x;
    float gm = g[c], gb = b[c];
    float s = 0.f;
    for (int l = 0; l < Lq; l++) {
        int row = bb*Lq + l;
        s += (X[(size_t)row*Dq + c] - mean[row]) * rstd[row] * gm + gb;
    }
    float v = s / (float)Lq;
    fid[bb*Dq + c] = v;
    out[bb*Dq + c] = v;
}

__global__ void feat_bn(const float* __restrict__ fid, const float* __restrict__ g,
                        const float* __restrict__ b, float* __restrict__ out)
{
    int c = blockIdx.x * blockDim.x + threadIdx.x;
    if (c >= Dq) return;
    float s = 0.f, ss = 0.f;
    for (int bb = 0; bb < Bq; bb++) {
        float v = fid[bb*Dq + c]; s += v; ss += v*v;
    }
    float m = s / (float)Bq;
    float var = ss / (float)Bq - m*m;
    float rs = rsqrtf(var + EPSq);
    for (int bb = 0; bb < Bq; bb++)
        out[bb*Dq + c] = (fid[bb*Dq + c] - m) * rs * g[c] + b[c];
}

// ---------------- host ----------------
#define GETSYM(p, s) { void* _t; cudaGetSymbolAddress(&_t, s); p = (float*)_t; }

extern "C" void kernel_launch(void* const* d_in, const int* in_sizes, int n_in,
                              void* d_out, int out_size)
{
    const float* x        = (const float*)d_in[0];
    const float* sq_w     = (const float*)d_in[1];
    const float* sq_bn_g  = (const float*)d_in[2];
    const float* sq_bn_b  = (const float*)d_in[3];
    const float* dw_w     = (const float*)d_in[4];
    const float* dw_bn_g  = (const float*)d_in[5];
    const float* dw_bn_b  = (const float*)d_in[6];
    const float* ex_w     = (const float*)d_in[7];
    const float* ex_bn_g  = (const float*)d_in[8];
    const float* ex_bn_b  = (const float*)d_in[9];
    const float* attr_g   = (const float*)d_in[10];
    const float* attr_b   = (const float*)d_in[11];
    const float* mnorm_g  = (const float*)d_in[12];
    const float* mnorm_b  = (const float*)d_in[13];
    const float* in_proj_w= (const float*)d_in[14];
    const float* conv_w   = (const float*)d_in[15];
    const float* conv_b   = (const float*)d_in[16];
    const float* xproj_w  = (const float*)d_in[17];
    const float* dtproj_w = (const float*)d_in[18];
    const float* dtproj_b = (const float*)d_in[19];
    const float* A_log    = (const float*)d_in[20];
    const float* D_param  = (const float*)d_in[21];
    const float* out_proj_w = (const float*)d_in[22];
    const float* gate_w   = (const float*)d_in[23];
    const float* gate_b   = (const float*)d_in[24];
    const float* idn_g    = (const float*)d_in[25];
    const float* idn_b    = (const float*)d_in[26];
    const float* idbn_g   = (const float*)d_in[27];
    const float* idbn_b   = (const float*)d_in[28];
    float* out = (float*)d_out;

    float *h0,*tmpH,*h2,*e,*x1,*xn,*xz,*xm2,*dbc,*del,*y,*mo,*gl,*xf;
    float *rm,*rs,*rm2,*rs2,*fid,*stats,*xr,*wr;
    GETSYM(h0, g_h0);   GETSYM(tmpH, g_tmpH); GETSYM(h2, g_h2);
    GETSYM(e, g_e);     GETSYM(x1, g_x1);     GETSYM(xn, g_xn);
    GETSYM(xz, g_xz);   GETSYM(xm2, g_xm2);   GETSYM(dbc, g_dbc);
    GETSYM(del, g_del); GETSYM(y, g_y);       GETSYM(mo, g_mo);
    GETSYM(gl, g_gl);   GETSYM(xf, g_xf);
    GETSYM(rm, g_rm);   GETSYM(rs, g_rs);     GETSYM(rm2, g_rm2); GETSYM(rs2, g_rs2);
    GETSYM(fid, g_fid); GETSYM(stats, g_stats);
    GETSYM(xr, g_xr);   GETSYM(wr, g_wr);

    float* sum1 = stats + ST_SUM1;
    float* sq1  = stats + ST_SQ1;
    float* sum2 = stats + ST_SUM2;
    float* sq2  = stats + ST_SQ2;
    float* sum3 = stats + ST_SUM3;
    float* sq3  = stats + ST_SQ3;

    static cudaStream_t s1 = 0;
    static cudaEvent_t evW0 = 0, evWdone = 0, evFork = 0, evZ = 0, evJoin = 0;
    static int smemSet = 0;
    if (!s1) {
        cudaStreamCreateWithFlags(&s1, cudaStreamNonBlocking);
        cudaEventCreateWithFlags(&evW0, cudaEventDisableTiming);
        cudaEventCreateWithFlags(&evWdone, cudaEventDisableTiming);
        cudaEventCreateWithFlags(&evFork, cudaEventDisableTiming);
        cudaEventCreateWithFlags(&evZ, cudaEventDisableTiming);
        cudaEventCreateWithFlags(&evJoin, cudaEventDisableTiming);
    }
    if (!smemSet) {
        cudaFuncSetAttribute(gemm_tc<0>, cudaFuncAttributeMaxDynamicSharedMemorySize, GEMM_DSMEM);
        cudaFuncSetAttribute(gemm_tc<1>, cudaFuncAttributeMaxDynamicSharedMemorySize, GEMM_DSMEM);
        cudaFuncSetAttribute(gemm_tc<2>, cudaFuncAttributeMaxDynamicSharedMemorySize, GEMM_DSMEM);
        cudaFuncSetAttribute(gemm_tc<3>, cudaFuncAttributeMaxDynamicSharedMemorySize, GEMM_DSMEM);
        smemSet = 1;
    }

    const int T = 256;
    dim3 gHID((Nq*HIDq + T-1)/T), gDI((Nq*DIq + T-1)/T);

    cudaMemsetAsync(stats, 0, ST_TOTAL*sizeof(float));

    // 0) rounds needed immediately on main: x, sq_w
    round_tf32<<<(Nq*Dq/4 + 255)/256, 256>>>(x, xr, Nq*Dq/4);
    round_tf32<<<(HIDq*Dq/4 + 255)/256, 256>>>(sq_w, wr + W_SQ, HIDq*Dq/4);
    // remaining weight rounds on side stream (hidden under squeeze phase)
    cudaEventRecord(evW0, 0);
    cudaStreamWaitEvent(s1, evW0, 0);
    round_tf32<<<(Dq*HIDq/4 + 255)/256, 256, 0, s1>>>(ex_w, wr + W_EX, Dq*HIDq/4);
    round_tf32<<<(2*DIq*Dq/4 + 255)/256, 256, 0, s1>>>(in_proj_w, wr + W_INP, 2*DIq*Dq/4);
    round_tf32<<<(80*DIq/4 + 255)/256, 256, 0, s1>>>(xproj_w,  wr + W_XP,  80*DIq/4);
    round_tf32<<<(DIq*DTRq/4 + 255)/256, 256, 0, s1>>>(dtproj_w, wr + W_DT, DIq*DTRq/4);
    round_tf32<<<(Dq*DIq/4 + 255)/256, 256, 0, s1>>>(out_proj_w, wr + W_OUT, Dq*DIq/4);
    round_tf32<<<(Dq*Dq/4 + 255)/256, 256, 0, s1>>>(gate_w, wr + W_GATE, Dq*Dq/4);
    cudaEventRecord(evWdone, s1);

    // 1) squeeze GEMM (fused BN stats) + BN+SiLU
    gemm_tc<3><<<dim3(2, Nq/128), 256, GEMM_DSMEM>>>(xr, Dq, wr + W_SQ, h0, HIDq, HIDq, Dq, 0, sum1, sq1);
    bn_silu<<<gHID, T>>>(h0, h0, sum1, sq1, sq_bn_g, sq_bn_b, Nq, HIDq);

    // 2) dwconv K=5 + BN+SiLU
    dwconv5<<<gHID, T>>>(h0, dw_w, tmpH);
    bn_stats<<<dim3(256,1), T>>>(tmpH, Nq, HIDq, sum2, sq2);
    bn_silu<<<gHID, T>>>(tmpH, h2, sum2, sq2, dw_bn_g, dw_bn_b, Nq, HIDq);

    // 3) excite GEMM (fused BN stats) + fused bn_add + LN
    cudaStreamWaitEvent(0, evWdone, 0);
    gemm_tc<3><<<dim3(6, Nq/128), 256, GEMM_DSMEM>>>(h2, HIDq, wr + W_EX, e, Dq, Dq, HIDq, 0, sum3, sq3);
    bn_add_ln<<<Nq, T>>>(e, x, sum3, sq3, ex_bn_g, ex_bn_b, mnorm_g, mnorm_b,
                         x1, xn, rm, rs);

    // fork: side stream z-half of in_proj, feat_attr, gate GEMM
    cudaEventRecord(evFork, 0);
    cudaStreamWaitEvent(s1, evFork, 0);
    gemm_tc<0><<<dim3(12, Nq/128), 256, GEMM_DSMEM, s1>>>(
        xn, Dq, wr + W_INP + (size_t)DIq*Dq, xz + DIq, DIq, 2*DIq, Dq, 0, 0, 0);
    cudaEventRecord(evZ, s1);
    attr_max<<<dim3(Bq,3), T, 0, s1>>>(x1, rm, rs, attr_g, attr_b, out);
    gemm_tc<0><<<dim3(6, Nq/128), 256, GEMM_DSMEM, s1>>>(xn, Dq, wr + W_GATE, gl, Dq, Dq, Dq, 0, 0, 0);
    cudaEventRecord(evJoin, s1);

    // 5) main: xm-half of in_proj
    gemm_tc<0><<<dim3(12, Nq/128), 256, GEMM_DSMEM>>>(
        xn, Dq, wr + W_INP, xz, DIq, 2*DIq, Dq, 0, 0, 0);

    // 6) causal conv + silu
    conv_causal_silu<<<gDI, T>>>(xz, conv_w, conv_b, xm2);

    // 7) x_proj (rounded store); dt_proj (+softplus)
    gemm_tc<2><<<dim3(1, Nq/128), 256, GEMM_DSMEM>>>(xm2, DIq, wr + W_XP, dbc, 80, 80, DIq, 0, 0, 0);
    gemm_tc<1><<<dim3(12, Nq/128), 256, GEMM_DSMEM>>>(dbc, 80, wr + W_DT, del, DIq, DIq, DTRq, dtproj_b, 0, 0);

    // 8) selective scan (needs z-half)
    cudaStreamWaitEvent(0, evZ, 0);
    scan_k<<<dim3(DIq/128, Bq), 128>>>(del, xm2, dbc, xz, A_log, D_param, y);

    // 9) out_proj; join gate; fused combine + LN stats
    gemm_tc<0><<<dim3(6, Nq/128), 256, GEMM_DSMEM>>>(y, DIq, wr + W_OUT, mo, Dq, Dq, DIq, 0, 0, 0);
    cudaStreamWaitEvent(0, evJoin, 0);
    combine_ln<<<Nq, T>>>(x, x1, mo, gl, gate_b, xf, rm2, rs2);

    // 10) feat_id + feat_id_bn
    feat_id_k<<<dim3(Bq,3), T>>>(xf, rm2, rs2, idn_g, idn_b, fid, out + Bq*Dq);
    feat_bn<<<3, T>>>(fid, idbn_g, idbn_b, out + 2*Bq*Dq);
}

// round 13
// speedup vs baseline: 1.0848x; 1.0049x over previous
#include <cuda_runtime.h>
#include <math.h>
#include <stdint.h>

#define Bq    32
#define Lq    512
#define Dq    768
#define HIDq  192
#define DIq   1536
#define DSq   16
#define DTRq  48
#define Nq    (Bq*Lq)        // 16384
#define EPSq  1e-5f

// ---------------- scratch ----------------
__device__ __align__(256) float g_h0  [Nq*HIDq];
__device__ __align__(256) float g_tmpH[Nq*HIDq];
__device__ __align__(256) float g_h2  [Nq*HIDq];
__device__ __align__(256) float g_e   [Nq*Dq];
__device__ __align__(256) float g_x1  [Nq*Dq];
__device__ __align__(256) float g_xn  [Nq*Dq];
__device__ __align__(256) float g_xz  [Nq*2*DIq];
__device__ __align__(256) float g_xm2 [Nq*DIq];
__device__ __align__(256) float g_dbc [Nq*80];
__device__ __align__(256) float g_del [Nq*DIq];
__device__ __align__(256) float g_y   [Nq*DIq];
__device__ __align__(256) float g_mo  [Nq*Dq];
__device__ __align__(256) float g_gl  [Nq*Dq];
__device__ __align__(256) float g_xf  [Nq*Dq];
__device__ __align__(256) float g_rm  [Nq];
__device__ __align__(256) float g_rs  [Nq];
__device__ __align__(256) float g_rm2 [Nq];
__device__ __align__(256) float g_rs2 [Nq];
__device__ __align__(256) float g_fid [Bq*Dq];
__device__ __align__(256) float g_xr  [Nq*Dq];     // tf32-rounded x
#define W_SQ   0
#define W_EX   (W_SQ  + HIDq*Dq)
#define W_INP  (W_EX  + Dq*HIDq)
#define W_XP   (W_INP + 2*DIq*Dq)
#define W_DT   (W_XP  + 80*DIq)
#define W_OUT  (W_DT  + DIq*DTRq)
#define W_GATE (W_OUT + Dq*DIq)
#define W_TOT  (W_GATE + Dq*Dq)
__device__ __align__(256) float g_wr[W_TOT];
#define ST_SUM1   0
#define ST_SQ1    (ST_SUM1+192)
#define ST_SUM2   (ST_SQ1+192)
#define ST_SQ2    (ST_SUM2+192)
#define ST_SUM3   (ST_SQ2+192)
#define ST_SQ3    (ST_SUM3+768)
#define ST_TOTAL  (ST_SQ3+768)
__device__ __align__(256) float g_stats[ST_TOTAL];

// ================= helpers =================
__device__ __forceinline__ uint32_t f2tf(float f) {
    uint32_t u;
    asm("cvt.rna.tf32.f32 %0, %1;" : "=r"(u) : "f"(f));
    return u;
}
__device__ __forceinline__ float f2tf_f(float f) { return __uint_as_float(f2tf(f)); }

__device__ __forceinline__ void mma_tf32(float* d, const uint32_t* a, const uint32_t* b) {
    asm volatile(
        "mma.sync.aligned.m16n8k8.row.col.f32.tf32.tf32.f32 "
        "{%0,%1,%2,%3}, {%4,%5,%6,%7}, {%8,%9}, {%0,%1,%2,%3};"
        : "+f"(d[0]), "+f"(d[1]), "+f"(d[2]), "+f"(d[3])
        : "r"(a[0]), "r"(a[1]), "r"(a[2]), "r"(a[3]), "r"(b[0]), "r"(b[1]));
}

__device__ __forceinline__ uint32_t smem_u32(const void* p) {
    uint32_t a;
    asm("{ .reg .u64 t; cvta.to.shared.u64 t, %1; cvt.u32.u64 %0, t; }" : "=r"(a) : "l"(p));
    return a;
}
#define CP_ASYNC(dst, src, sz) \
    asm volatile("cp.async.cg.shared.global [%0], [%1], 16, %2;" \
                 :: "r"(dst), "l"(src), "r"(sz) : "memory")
#define CP_COMMIT() asm volatile("cp.async.commit_group;" ::: "memory")
#define CP_WAIT(n)  asm volatile("cp.async.wait_group %0;" :: "n"(n) : "memory")

// ================= TF32 GEMM: cp.async staged, 2 CTAs/SM =================
// C[M,Nc] = A[M,K](lda) @ W[Nc,K]^T, C row stride ldc. Inputs PRE-ROUNDED to tf32.
// MODE 0: plain store. MODE 1: softplus(v+p0[c]). MODE 2: tf32-rounded store.
// MODE 3: plain store + per-channel sum/sq atomics. MODE 4: split-K atomicAdd
//         (blockIdx.z selects K-half; C must be zero-initialized).
#define SA 36
#define TILE_U (128*SA)
#define GEMM_DSMEM (2*2*TILE_U*4)

template<int MODE>
__global__ void __launch_bounds__(256, 2) gemm_tc(
    const float* __restrict__ A, int lda,
    const float* __restrict__ W,
    float* __restrict__ C, int Nc, int ldc, int K,
    const float* __restrict__ p0,
    float* __restrict__ psum, float* __restrict__ psq)
{
    extern __shared__ uint32_t dsm[];
    const uint32_t sbase = smem_u32(dsm);

    const int bm = blockIdx.y * 128;
    const int bn = blockIdx.x * 128;
    const int t  = threadIdx.x;
    const int wid  = t >> 5;
    const int lane = t & 31;
    const int qr = lane >> 2;
    const int qc = lane & 3;
    const int warp_m = wid & 3;
    const int warp_n = wid >> 2;

    int kBase = 0, kLen = K;
    if (MODE == 4) { kLen = K >> 1; kBase = blockIdx.z * kLen; }

    const int r0t = t >> 3;
    const int c4  = (t & 7) * 4;

    const float* aRow[4];
    const float* bRow[4];
    int bOk[4];
    uint32_t dstOff[4];
    #pragma unroll
    for (int i = 0; i < 4; i++) {
        int r = r0t + i*32;
        aRow[i] = A + (size_t)(bm + r)*lda + kBase;
        int j = bn + r;
        bOk[i] = (j < Nc);
        bRow[i] = W + (size_t)(bOk[i] ? j : 0)*K + kBase;
        dstOff[i] = (uint32_t)(r*SA + c4) * 4u;
    }

    float acc[2][8][4];
    #pragma unroll
    for (int mt = 0; mt < 2; mt++)
        #pragma unroll
        for (int nt = 0; nt < 8; nt++)
            #pragma unroll
            for (int q = 0; q < 4; q++) acc[mt][nt][q] = 0.f;

    const int NC = (kLen + 31) / 32;

    {
        int k = c4;
        int szA = (k < kLen) ? 16 : 0;
        #pragma unroll
        for (int i = 0; i < 4; i++)
            CP_ASYNC(sbase + dstOff[i], aRow[i] + k, szA);
        #pragma unroll
        for (int i = 0; i < 4; i++) {
            int szB = (bOk[i] && k < kLen) ? 16 : 0;
            CP_ASYNC(sbase + (uint32_t)TILE_U*4 + dstOff[i], bRow[i] + k, szB);
        }
        CP_COMMIT();
    }

    for (int ch = 0; ch < NC; ch++) {
        const int buf = ch & 1;
        if (ch + 1 < NC) {
            const int k = (ch + 1)*32 + c4;
            uint32_t base = sbase + (uint32_t)(buf ^ 1) * 2u * TILE_U * 4u;
            int szA = (k < kLen) ? 16 : 0;
            #pragma unroll
            for (int i = 0; i < 4; i++)
                CP_ASYNC(base + dstOff[i], aRow[i] + k, szA);
            #pragma unroll
            for (int i = 0; i < 4; i++) {
                int szB = (bOk[i] && k < kLen) ? 16 : 0;
                CP_ASYNC(base + (uint32_t)TILE_U*4 + dstOff[i], bRow[i] + k, szB);
            }
            CP_COMMIT();
            CP_WAIT(1);
        } else {
            CP_WAIT(0);
        }
        __syncthreads();

        const uint32_t* As = dsm + (size_t)buf * 2 * TILE_U;
        const uint32_t* Bs = As + TILE_U;
        #pragma unroll
        for (int ks = 0; ks < 4; ks++) {
            const int k0 = ks * 8;
            uint32_t afr[2][4];
            #pragma unroll
            for (int mt = 0; mt < 2; mt++) {
                int r0 = warp_m*32 + mt*16 + qr;
                afr[mt][0] = As[r0*SA + k0 + qc];
                afr[mt][1] = As[(r0+8)*SA + k0 + qc];
                afr[mt][2] = As[r0*SA + k0 + qc + 4];
                afr[mt][3] = As[(r0+8)*SA + k0 + qc + 4];
            }
            uint32_t bfr[8][2];
            #pragma unroll
            for (int nt = 0; nt < 8; nt++) {
                int n = warp_n*64 + nt*8 + qr;
                bfr[nt][0] = Bs[n*SA + k0 + qc];
                bfr[nt][1] = Bs[n*SA + k0 + qc + 4];
            }
            #pragma unroll
            for (int mt = 0; mt < 2; mt++)
                #pragma unroll
                for (int nt = 0; nt < 8; nt++)
                    mma_tf32(acc[mt][nt], afr[mt], bfr[nt]);
        }
        __syncthreads();
    }

    if (MODE == 0 || MODE == 2) {
        #pragma unroll
        for (int mt = 0; mt < 2; mt++) {
            int r0 = bm + warp_m*32 + mt*16 + qr;
            #pragma unroll
            for (int nt = 0; nt < 8; nt++) {
                int c = bn + warp_n*64 + nt*8 + qc*2;
                if (c < Nc) {
                    float v0 = acc[mt][nt][0], v1 = acc[mt][nt][1];
                    float v2 = acc[mt][nt][2], v3 = acc[mt][nt][3];
                    if (MODE == 2) { v0 = f2tf_f(v0); v1 = f2tf_f(v1); v2 = f2tf_f(v2); v3 = f2tf_f(v3); }
                    *(float2*)&C[(size_t)r0*ldc + c]     = make_float2(v0, v1);
                    *(float2*)&C[(size_t)(r0+8)*ldc + c] = make_float2(v2, v3);
                }
            }
        }
    } else if (MODE == 1) {
        #pragma unroll
        for (int mt = 0; mt < 2; mt++) {
            int r0 = bm + warp_m*32 + mt*16 + qr;
            #pragma unroll
            for (int nt = 0; nt < 8; nt++) {
                int c = bn + warp_n*64 + nt*8 + qc*2;
                if (c < Nc) {
                    float b0 = p0[c], b1 = p0[c+1];
                    float v;
                    v = acc[mt][nt][0] + b0; v = (v > 20.f) ? v : log1pf(__expf(v));
                    C[(size_t)r0*ldc + c] = v;
                    v = acc[mt][nt][1] + b1; v = (v > 20.f) ? v : log1pf(__expf(v));
                    C[(size_t)r0*ldc + c + 1] = v;
                    v = acc[mt][nt][2] + b0; v = (v > 20.f) ? v : log1pf(__expf(v));
                    C[(size_t)(r0+8)*ldc + c] = v;
                    v = acc[mt][nt][3] + b1; v = (v > 20.f) ? v : log1pf(__expf(v));
                    C[(size_t)(r0+8)*ldc + c + 1] = v;
                }
            }
        }
    } else if (MODE == 4) {
        #pragma unroll
        for (int mt = 0; mt < 2; mt++) {
            int r0 = bm + warp_m*32 + mt*16 + qr;
            #pragma unroll
            for (int nt = 0; nt < 8; nt++) {
                int c = bn + warp_n*64 + nt*8 + qc*2;
                if (c < Nc) {
                    atomicAdd(&C[(size_t)r0*ldc + c],     acc[mt][nt][0]);
                    atomicAdd(&C[(size_t)r0*ldc + c + 1], acc[mt][nt][1]);
                    atomicAdd(&C[(size_t)(r0+8)*ldc + c],     acc[mt][nt][2]);
                    atomicAdd(&C[(size_t)(r0+8)*ldc + c + 1], acc[mt][nt][3]);
                }
            }
        }
    } else {
        // MODE 3: store + per-channel stats
        float s[16], ss[16];
        #pragma unroll
        for (int i = 0; i < 16; i++) { s[i] = 0.f; ss[i] = 0.f; }
        #pragma unroll
        for (int mt = 0; mt < 2; mt++) {
            int r0 = bm + warp_m*32 + mt*16 + qr;
            #pragma unroll
            for (int nt = 0; nt < 8; nt++) {
                int c = bn + warp_n*64 + nt*8 + qc*2;
                if (c < Nc) {
                    *(float2*)&C[(size_t)r0*ldc + c]     = make_float2(acc[mt][nt][0], acc[mt][nt][1]);
                    *(float2*)&C[(size_t)(r0+8)*ldc + c] = make_float2(acc[mt][nt][2], acc[mt][nt][3]);
                    #pragma unroll
                    for (int h = 0; h < 2; h++) {
                        float v0 = acc[mt][nt][h], v1 = acc[mt][nt][h+2];
                        s[nt*2+h]  += v0 + v1;
                        ss[nt*2+h] += v0*v0 + v1*v1;
                    }
                }
            }
        }
        #pragma unroll
        for (int o = 4; o < 32; o <<= 1) {
            #pragma unroll
            for (int i = 0; i < 16; i++) {
                s[i]  += __shfl_xor_sync(0xffffffffu, s[i], o);
                ss[i] += __shfl_xor_sync(0xffffffffu, ss[i], o);
            }
        }
        if (qr == 0) {
            #pragma unroll
            for (int nt = 0; nt < 8; nt++)
                #pragma unroll
                for (int h = 0; h < 2; h++) {
                    int c = bn + warp_n*64 + nt*8 + qc*2 + h;
                    if (c < Nc) {
                        atomicAdd(&psum[c], s[nt*2+h]);
                        atomicAdd(&psq[c],  ss[nt*2+h]);
                    }
                }
        }
    }
}

// ---------------- tf32 pre-round ----------------
__global__ void round_tf32(const float* __restrict__ X, float* __restrict__ Y, int n4)
{
    int i = blockIdx.x * blockDim.x + threadIdx.x;
    if (i >= n4) return;
    float4 v = ((const float4*)X)[i];
    v.x = f2tf_f(v.x); v.y = f2tf_f(v.y); v.z = f2tf_f(v.z); v.w = f2tf_f(v.w);
    ((float4*)Y)[i] = v;
}

// ---------------- BatchNorm stats ----------------
__global__ void bn_stats(const float* __restrict__ X, int M, int C,
                         float* __restrict__ sum, float* __restrict__ sq)
{
    int c = blockIdx.y * blockDim.x + threadIdx.x;
    if (c >= C) return;
    int rows = M / gridDim.x;
    int r0 = blockIdx.x * rows;
    float s = 0.f, ss = 0.f;
    for (int r = r0; r < r0 + rows; r++) {
        float v = X[(size_t)r*C + c];
        s += v; ss += v*v;
    }
    atomicAdd(&sum[c], s);
    atomicAdd(&sq[c],  ss);
}

__global__ void bn_silu(const float* __restrict__ X, float* __restrict__ Y,
                        const float* __restrict__ sum, const float* __restrict__ sq,
                        const float* __restrict__ g, const float* __restrict__ b,
                        int M, int C)
{
    int idx = blockIdx.x * blockDim.x + threadIdx.x;
    if (idx >= M*C) return;
    int c = idx % C;
    float mean = sum[c] / (float)M;
    float var  = sq[c] / (float)M - mean*mean;
    float v = (X[idx] - mean) * rsqrtf(var + EPSq) * g[c] + b[c];
    Y[idx] = f2tf_f(v / (1.f + __expf(-v)));
}

// ---------------- depthwise conv K=5 ----------------
__global__ void dwconv5(const float* __restrict__ X, const float* __restrict__ w,
                        float* __restrict__ Y)
{
    int idx = blockIdx.x * blockDim.x + threadIdx.x;
    if (idx >= Nq*HIDq) return;
    int c  = idx % HIDq;
    int l  = (idx / HIDq) % Lq;
    int bb = idx / (HIDq*Lq);
    const float* xb = X + (size_t)bb*Lq*HIDq;
    float acc = 0.f;
    #pragma unroll
    for (int k = 0; k < 5; k++) {
        int ls = l - 2 + k;
        if (ls >= 0 && ls < Lq) acc += xb[(size_t)ls*HIDq + c] * w[c*5 + k];
    }
    Y[idx] = acc;
}

// ---------------- bn_add + LN, fused ----------------
__global__ void __launch_bounds__(256) bn_add_ln(
    const float* __restrict__ E, const float* __restrict__ X,
    const float* __restrict__ sum3, const float* __restrict__ sq3,
    const float* __restrict__ exg, const float* __restrict__ exb,
    const float* __restrict__ lng, const float* __restrict__ lnb,
    float* __restrict__ X1, float* __restrict__ XN,
    float* __restrict__ rm, float* __restrict__ rs)
{
    const int row = blockIdx.x;
    const int tid = threadIdx.x;
    float vloc[3];
    float s = 0.f, ss = 0.f;
    #pragma unroll
    for (int j = 0; j < 3; j++) {
        int c = tid + j*256;
        float mean = sum3[c] / (float)Nq;
        float var  = sq3[c] / (float)Nq - mean*mean;
        float ga = rsqrtf(var + EPSq) * exg[c];
        float be = exb[c] - mean*ga;
        float v = X[(size_t)row*Dq + c] + E[(size_t)row*Dq + c]*ga + be;
        vloc[j] = v;
        s += v; ss += v*v;
    }
    __shared__ float sh1[8], sh2[8], bcast[2];
    for (int o = 16; o; o >>= 1) {
        s  += __shfl_down_sync(0xffffffffu, s, o);
        ss += __shfl_down_sync(0xffffffffu, ss, o);
    }
    int lane = tid & 31, warp = tid >> 5;
    if (lane == 0) { sh1[warp] = s; sh2[warp] = ss; }
    __syncthreads();
    if (tid == 0) {
        s = 0.f; ss = 0.f;
        #pragma unroll
        for (int wv = 0; wv < 8; wv++) { s += sh1[wv]; ss += sh2[wv]; }
        float m = s / (float)Dq;
        float v = ss / (float)Dq - m*m;
        float r = rsqrtf(v + EPSq);
        bcast[0] = m; bcast[1] = r;
        rm[row] = m; rs[row] = r;
    }
    __syncthreads();
    float m = bcast[0], r = bcast[1];
    #pragma unroll
    for (int j = 0; j < 3; j++) {
        int c = tid + j*256;
        X1[(size_t)row*Dq + c] = vloc[j];
        XN[(size_t)row*Dq + c] = f2tf_f((vloc[j] - m) * r * lng[c] + lnb[c]);
    }
}

// ---------------- combine + LN stats, fused ----------------
__global__ void __launch_bounds__(256) combine_ln(
    const float* __restrict__ X, const float* __restrict__ X1,
    const float* __restrict__ MO, const float* __restrict__ GL,
    const float* __restrict__ gb,
    float* __restrict__ XF, float* __restrict__ rm2, float* __restrict__ rs2)
{
    const int row = blockIdx.x;
    const int tid = threadIdx.x;
    float vloc[3];
    float s = 0.f, ss = 0.f;
    #pragma unroll
    for (int j = 0; j < 3; j++) {
        int c = tid + j*256;
        size_t i = (size_t)row*Dq + c;
        float gate = 1.f / (1.f + __expf(-(GL[i] + gb[c])));
        float v = X1[i] + MO[i]*gate + X[i];
        vloc[j] = v;
        s += v; ss += v*v;
    }
    __shared__ float sh1[8], sh2[8];
    for (int o = 16; o; o >>= 1) {
        s  += __shfl_down_sync(0xffffffffu, s, o);
        ss += __shfl_down_sync(0xffffffffu, ss, o);
    }
    int lane = tid & 31, warp = tid >> 5;
    if (lane == 0) { sh1[warp] = s; sh2[warp] = ss; }
    __syncthreads();
    if (tid == 0) {
        s = 0.f; ss = 0.f;
        #pragma unroll
        for (int wv = 0; wv < 8; wv++) { s += sh1[wv]; ss += sh2[wv]; }
        float m = s / (float)Dq;
        float v = ss / (float)Dq - m*m;
        rm2[row] = m;
        rs2[row] = rsqrtf(v + EPSq);
    }
    #pragma unroll
    for (int j = 0; j < 3; j++) {
        int c = tid + j*256;
        XF[(size_t)row*Dq + c] = vloc[j];
    }
}

// ---------------- causal conv K=4 + bias + silu ----------------
__global__ void conv_causal_silu(const float* __restrict__ XZ, const float* __restrict__ w,
                                 const float* __restrict__ bias, float* __restrict__ Y)
{
    int idx = blockIdx.x * blockDim.x + threadIdx.x;
    if (idx >= Nq*DIq) return;
    int c  = idx % DIq;
    int l  = (idx / DIq) % Lq;
    int bb = idx / (DIq*Lq);
    float acc = bias[c];
    #pragma unroll
    for (int k = 0; k < 4; k++) {
        int ls = l - 3 + k;
        if (ls >= 0) acc += XZ[(size_t)(bb*Lq + ls)*(2*DIq) + c] * w[c*4 + k];
    }
    Y[idx] = f2tf_f(acc / (1.f + __expf(-acc)));
}

// feat_attr
__global__ void attr_max(const float* __restrict__ X, const float* __restrict__ mean,
                         const float* __restrict__ rstd, const float* __restrict__ g,
                         const float* __restrict__ b, float* __restrict__ out)
{
    int c  = blockIdx.y * blockDim.x + threadIdx.x;
    int bb = blockIdx.x;
    float gm = g[c], gb = b[c];
    float mx = -3.4e38f;
    for (int l = 0; l < Lq; l++) {
        int row = bb*Lq + l;
        float v = (X[(size_t)row*Dq + c] - mean[row]) * rstd[row] * gm + gb;
        mx = fmaxf(mx, v);
    }
    out[bb*Dq + c] = mx;
}

// ---------------- selective scan ----------------
__global__ void __launch_bounds__(128) scan_k(
    const float* __restrict__ delta, const float* __restrict__ u,
    const float* __restrict__ dbc,   const float* __restrict__ xz,
    const float* __restrict__ A_log, const float* __restrict__ Dp,
    float* __restrict__ y)
{
    __shared__ float Bs[128][DSq];
    __shared__ float Cs[128][DSq];
    const int bb = blockIdx.y;
    const int d  = blockIdx.x * 128 + threadIdx.x;

    float A[DSq], h[DSq];
    bool fast = true;
    #pragma unroll
    for (int s = 0; s < DSq; s++) {
        A[s] = -expf(A_log[d*DSq + s]);
        h[s] = 0.f;
        if (fabsf(A[s] + (float)(s+1)) > 1e-3f * (float)(s+1)) fast = false;
    }
    const float dp = Dp[d];

    for (int c0 = 0; c0 < Lq; c0 += 128) {
        for (int i = threadIdx.x; i < 128*DSq; i += 128) {
            int l = i >> 4, s = i & 15;
            size_t row = (size_t)(bb*Lq + c0 + l);
            Bs[l][s] = dbc[row*80 + DTRq + s];
            Cs[l][s] = dbc[row*80 + DTRq + DSq + s];
        }
        __syncthreads();
        size_t row0 = (size_t)(bb*Lq + c0);
        float dv = delta[row0*DIq + d];
        float uv = u[row0*DIq + d];
        float zv = xz[row0*(2*DIq) + DIq + d];
        if (fast) {
            for (int l = 0; l < 128; l++) {
                float nd = 0.f, nu = 0.f, nz = 0.f;
                if (l < 127) {
                    size_t rn = row0 + l + 1;
                    nd = delta[rn*DIq + d];
                    nu = u[rn*DIq + d];
                    nz = xz[rn*(2*DIq) + DIq + d];
                }
                float du = dv * uv;
                float e1 = __expf(-dv);
                float p = e1;
                float acc = 0.f;
                #pragma unroll
                for (int s = 0; s < DSq; s++) {
                    h[s] = h[s] * p + du * Bs[l][s];
                    acc  = fmaf(h[s], Cs[l][s], acc);
                    p *= e1;
                }
                float sz = zv / (1.f + __expf(-zv));
                y[(row0 + l)*DIq + d] = f2tf_f((acc + uv*dp) * sz);
                dv = nd; uv = nu; zv = nz;
            }
        } else {
            for (int l = 0; l < 128; l++) {
                float nd = 0.f, nu = 0.f, nz = 0.f;
                if (l < 127) {
                    size_t rn = row0 + l + 1;
                    nd = delta[rn*DIq + d];
                    nu = u[rn*DIq + d];
                    nz = xz[rn*(2*DIq) + DIq + d];
                }
                float du = dv * uv;
                float acc = 0.f;
                #pragma unroll
                for (int s = 0; s < DSq; s++) {
                    h[s] = h[s] * __expf(dv * A[s]) + du * Bs[l][s];
                    acc  = fmaf(h[s], Cs[l][s], acc);
                }
                float sz = zv / (1.f + __expf(-zv));
                y[(row0 + l)*DIq + d] = f2tf_f((acc + uv*dp) * sz);
                dv = nd; uv = nu; zv = nz;
            }
        }
        __syncthreads();
    }
}

// feat_id
__global__ void feat_id_k(const float* __restrict__ X, const float* __restrict__ mean,
                          const float* __restrict__ rstd, const float* __restrict__ g,
                          const float* __restrict__ b, float* __restrict__ fid,
                          float* __restrict__ out)
{
    int c  = blockIdx.y * blockDim.x + threadIdx.x;
    int bb = blockIdx.x;
    float gm = g[c], gb = b[c];
    float s = 0.f;
    for (int l = 0; l < Lq; l++) {
        int row = bb*Lq + l;
        s += (X[(size_t)row*Dq + c] - mean[row]) * rstd[row] * gm + gb;
    }
    float v = s / (float)Lq;
    fid[bb*Dq + c] = v;
    out[bb*Dq + c] = v;
}

__global__ void feat_bn(const float* __restrict__ fid, const float* __restrict__ g,
                        const float* __restrict__ b, float* __restrict__ out)
{
    int c = blockIdx.x * blockDim.x + threadIdx.x;
    if (c >= Dq) return;
    float s = 0.f, ss = 0.f;
    for (int bb = 0; bb < Bq; bb++) {
        float v = fid[bb*Dq + c]; s += v; ss += v*v;
    }
    float m = s / (float)Bq;
    float var = ss / (float)Bq - m*m;
    float rs = rsqrtf(var + EPSq);
    for (int bb = 0; bb < Bq; bb++)
        out[bb*Dq + c] = (fid[bb*Dq + c] - m) * rs * g[c] + b[c];
}

// ---------------- host ----------------
#define GETSYM(p, s) { void* _t; cudaGetSymbolAddress(&_t, s); p = (float*)_t; }

extern "C" void kernel_launch(void* const* d_in, const int* in_sizes, int n_in,
                              void* d_out, int out_size)
{
    const float* x        = (const float*)d_in[0];
    const float* sq_w     = (const float*)d_in[1];
    const float* sq_bn_g  = (const float*)d_in[2];
    const float* sq_bn_b  = (const float*)d_in[3];
    const float* dw_w     = (const float*)d_in[4];
    const float* dw_bn_g  = (const float*)d_in[5];
    const float* dw_bn_b  = (const float*)d_in[6];
    const float* ex_w     = (const float*)d_in[7];
    const float* ex_bn_g  = (const float*)d_in[8];
    const float* ex_bn_b  = (const float*)d_in[9];
    const float* attr_g   = (const float*)d_in[10];
    const float* attr_b   = (const float*)d_in[11];
    const float* mnorm_g  = (const float*)d_in[12];
    const float* mnorm_b  = (const float*)d_in[13];
    const float* in_proj_w= (const float*)d_in[14];
    const float* conv_w   = (const float*)d_in[15];
    const float* conv_b   = (const float*)d_in[16];
    const float* xproj_w  = (const float*)d_in[17];
    const float* dtproj_w = (const float*)d_in[18];
    const float* dtproj_b = (const float*)d_in[19];
    const float* A_log    = (const float*)d_in[20];
    const float* D_param  = (const float*)d_in[21];
    const float* out_proj_w = (const float*)d_in[22];
    const float* gate_w   = (const float*)d_in[23];
    const float* gate_b   = (const float*)d_in[24];
    const float* idn_g    = (const float*)d_in[25];
    const float* idn_b    = (const float*)d_in[26];
    const float* idbn_g   = (const float*)d_in[27];
    const float* idbn_b   = (const float*)d_in[28];
    float* out = (float*)d_out;

    float *h0,*tmpH,*h2,*e,*x1,*xn,*xz,*xm2,*dbc,*del,*y,*mo,*gl,*xf;
    float *rm,*rs,*rm2,*rs2,*fid,*stats,*xr,*wr;
    GETSYM(h0, g_h0);   GETSYM(tmpH, g_tmpH); GETSYM(h2, g_h2);
    GETSYM(e, g_e);     GETSYM(x1, g_x1);     GETSYM(xn, g_xn);
    GETSYM(xz, g_xz);   GETSYM(xm2, g_xm2);   GETSYM(dbc, g_dbc);
    GETSYM(del, g_del); GETSYM(y, g_y);       GETSYM(mo, g_mo);
    GETSYM(gl, g_gl);   GETSYM(xf, g_xf);
    GETSYM(rm, g_rm);   GETSYM(rs, g_rs);     GETSYM(rm2, g_rm2); GETSYM(rs2, g_rs2);
    GETSYM(fid, g_fid); GETSYM(stats, g_stats);
    GETSYM(xr, g_xr);   GETSYM(wr, g_wr);

    float* sum1 = stats + ST_SUM1;
    float* sq1  = stats + ST_SQ1;
    float* sum2 = stats + ST_SUM2;
    float* sq2  = stats + ST_SQ2;
    float* sum3 = stats + ST_SUM3;
    float* sq3  = stats + ST_SQ3;

    static cudaStream_t s1 = 0;
    static cudaEvent_t evW0 = 0, evWdone = 0, evFork = 0, evZ = 0, evJoin = 0;
    static int smemSet = 0;
    if (!s1) {
        cudaStreamCreateWithFlags(&s1, cudaStreamNonBlocking);
        cudaEventCreateWithFlags(&evW0, cudaEventDisableTiming);
        cudaEventCreateWithFlags(&evWdone, cudaEventDisableTiming);
        cudaEventCreateWithFlags(&evFork, cudaEventDisableTiming);
        cudaEventCreateWithFlags(&evZ, cudaEventDisableTiming);
        cudaEventCreateWithFlags(&evJoin, cudaEventDisableTiming);
    }
    if (!smemSet) {
        cudaFuncSetAttribute(gemm_tc<0>, cudaFuncAttributeMaxDynamicSharedMemorySize, GEMM_DSMEM);
        cudaFuncSetAttribute(gemm_tc<1>, cudaFuncAttributeMaxDynamicSharedMemorySize, GEMM_DSMEM);
        cudaFuncSetAttribute(gemm_tc<2>, cudaFuncAttributeMaxDynamicSharedMemorySize, GEMM_DSMEM);
        cudaFuncSetAttribute(gemm_tc<3>, cudaFuncAttributeMaxDynamicSharedMemorySize, GEMM_DSMEM);
        cudaFuncSetAttribute(gemm_tc<4>, cudaFuncAttributeMaxDynamicSharedMemorySize, GEMM_DSMEM);
        smemSet = 1;
    }

    const int T = 256;
    dim3 gHID((Nq*HIDq + T-1)/T), gDI((Nq*DIq + T-1)/T);

    cudaMemsetAsync(stats, 0, ST_TOTAL*sizeof(float));
    cudaMemsetAsync(dbc, 0, (size_t)Nq*80*sizeof(float));   // for split-K atomics

    // 0) rounds needed on main: x, sq_w, ex_w
    round_tf32<<<(Nq*Dq/4 + 255)/256, 256>>>(x, xr, Nq*Dq/4);
    round_tf32<<<(HIDq*Dq/4 + 255)/256, 256>>>(sq_w, wr + W_SQ, HIDq*Dq/4);
    round_tf32<<<(Dq*HIDq/4 + 255)/256, 256>>>(ex_w, wr + W_EX, Dq*HIDq/4);
    // remaining weight rounds on side stream
    cudaEventRecord(evW0, 0);
    cudaStreamWaitEvent(s1, evW0, 0);
    round_tf32<<<(2*DIq*Dq/4 + 255)/256, 256, 0, s1>>>(in_proj_w, wr + W_INP, 2*DIq*Dq/4);
    round_tf32<<<(80*DIq/4 + 255)/256, 256, 0, s1>>>(xproj_w,  wr + W_XP,  80*DIq/4);
    round_tf32<<<(DIq*DTRq/4 + 255)/256, 256, 0, s1>>>(dtproj_w, wr + W_DT, DIq*DTRq/4);
    round_tf32<<<(Dq*DIq/4 + 255)/256, 256, 0, s1>>>(out_proj_w, wr + W_OUT, Dq*DIq/4);
    round_tf32<<<(Dq*Dq/4 + 255)/256, 256, 0, s1>>>(gate_w, wr + W_GATE, Dq*Dq/4);
    cudaEventRecord(evWdone, s1);

    // 1) squeeze GEMM (fused BN stats) + BN+SiLU
    gemm_tc<3><<<dim3(2, Nq/128), 256, GEMM_DSMEM>>>(xr, Dq, wr + W_SQ, h0, HIDq, HIDq, Dq, 0, sum1, sq1);
    bn_silu<<<gHID, T>>>(h0, h0, sum1, sq1, sq_bn_g, sq_bn_b, Nq, HIDq);

    // 2) dwconv K=5 + BN+SiLU
    dwconv5<<<gHID, T>>>(h0, dw_w, tmpH);
    bn_stats<<<dim3(256,1), T>>>(tmpH, Nq, HIDq, sum2, sq2);
    bn_silu<<<gHID, T>>>(tmpH, h2, sum2, sq2, dw_bn_g, dw_bn_b, Nq, HIDq);

    // 3) excite GEMM (fused BN stats) + fused bn_add + LN (no cross-stream wait)
    gemm_tc<3><<<dim3(6, Nq/128), 256, GEMM_DSMEM>>>(h2, HIDq, wr + W_EX, e, Dq, Dq, HIDq, 0, sum3, sq3);
    bn_add_ln<<<Nq, T>>>(e, x, sum3, sq3, ex_bn_g, ex_bn_b, mnorm_g, mnorm_b,
                         x1, xn, rm, rs);

    // fork: side stream z-half of in_proj, feat_attr, gate GEMM
    // (s1's weight rounds precede these in stream order)
    cudaEventRecord(evFork, 0);
    cudaStreamWaitEvent(s1, evFork, 0);
    gemm_tc<0><<<dim3(12, Nq/128), 256, GEMM_DSMEM, s1>>>(
        xn, Dq, wr + W_INP + (size_t)DIq*Dq, xz + DIq, DIq, 2*DIq, Dq, 0, 0, 0);
    cudaEventRecord(evZ, s1);
    attr_max<<<dim3(Bq,3), T, 0, s1>>>(x1, rm, rs, attr_g, attr_b, out);
    gemm_tc<0><<<dim3(6, Nq/128), 256, GEMM_DSMEM, s1>>>(xn, Dq, wr + W_GATE, gl, Dq, Dq, Dq, 0, 0, 0);
    cudaEventRecord(evJoin, s1);

    // 5) main: xm-half of in_proj (first consumer of side-stream rounds)
    cudaStreamWaitEvent(0, evWdone, 0);
    gemm_tc<0><<<dim3(12, Nq/128), 256, GEMM_DSMEM>>>(
        xn, Dq, wr + W_INP, xz, DIq, 2*DIq, Dq, 0, 0, 0);

    // 6) causal conv + silu
    conv_causal_silu<<<gDI, T>>>(xz, conv_w, conv_b, xm2);

    // 7) x_proj split-K=2 (atomic) + tf32 re-round; dt_proj (+softplus)
    gemm_tc<4><<<dim3(1, Nq/128, 2), 256, GEMM_DSMEM>>>(xm2, DIq, wr + W_XP, dbc, 80, 80, DIq, 0, 0, 0);
    round_tf32<<<(Nq*80/4 + 255)/256, 256>>>(dbc, dbc, Nq*80/4);
    gemm_tc<1><<<dim3(12, Nq/128), 256, GEMM_DSMEM>>>(dbc, 80, wr + W_DT, del, DIq, DIq, DTRq, dtproj_b, 0, 0);

    // 8) selective scan (needs z-half)
    cudaStreamWaitEvent(0, evZ, 0);
    scan_k<<<dim3(DIq/128, Bq), 128>>>(del, xm2, dbc, xz, A_log, D_param, y);

    // 9) out_proj; join gate; fused combine + LN stats
    gemm_tc<0><<<dim3(6, Nq/128), 256, GEMM_DSMEM>>>(y, DIq, wr + W_OUT, mo, Dq, Dq, DIq, 0, 0, 0);
    cudaStreamWaitEvent(0, evJoin, 0);
    combine_ln<<<Nq, T>>>(x, x1, mo, gl, gate_b, xf, rm2, rs2);

    // 10) feat_id + feat_id_bn
    feat_id_k<<<dim3(Bq,3), T>>>(xf, rm2, rs2, idn_g, idn_b, fid, out + Bq*Dq);
    feat_bn<<<3, T>>>(fid, idbn_g, idbn_b, out + 2*Bq*Dq);
}

// round 14
// speedup vs baseline: 1.1110x; 1.0241x over previous
#include <cuda_runtime.h>
#include <math.h>
#include <stdint.h>

#define Bq    32
#define Lq    512
#define Dq    768
#define HIDq  192
#define DIq   1536
#define DSq   16
#define DTRq  48
#define Nq    (Bq*Lq)        // 16384
#define EPSq  1e-5f

// ---------------- scratch ----------------
__device__ __align__(256) float g_h0  [Nq*HIDq];
__device__ __align__(256) float g_tmpH[Nq*HIDq];
__device__ __align__(256) float g_h2  [Nq*HIDq];
__device__ __align__(256) float g_e   [Nq*Dq];
__device__ __align__(256) float g_x1  [Nq*Dq];
__device__ __align__(256) float g_xn  [Nq*Dq];
__device__ __align__(256) float g_xz  [Nq*2*DIq];
__device__ __align__(256) float g_xm2 [Nq*DIq];
__device__ __align__(256) float g_dbc [Nq*80];
__device__ __align__(256) float g_del [Nq*DIq];
__device__ __align__(256) float g_y   [Nq*DIq];
__device__ __align__(256) float g_mo  [Nq*Dq];
__device__ __align__(256) float g_gl  [Nq*Dq];
__device__ __align__(256) float g_xf  [Nq*Dq];
__device__ __align__(256) float g_rm  [Nq];
__device__ __align__(256) float g_rs  [Nq];
__device__ __align__(256) float g_rm2 [Nq];
__device__ __align__(256) float g_rs2 [Nq];
__device__ __align__(256) float g_fid [Bq*Dq];
__device__ __align__(256) float g_xr  [Nq*Dq];
#define W_SQ   0
#define W_EX   (W_SQ  + HIDq*Dq)
#define W_INP  (W_EX  + Dq*HIDq)
#define W_XP   (W_INP + 2*DIq*Dq)
#define W_DT   (W_XP  + 80*DIq)
#define W_OUT  (W_DT  + DIq*DTRq)
#define W_GATE (W_OUT + Dq*DIq)
#define W_TOT  (W_GATE + Dq*Dq)
__device__ __align__(256) float g_wr[W_TOT];
#define ST_SUM1   0
#define ST_SQ1    (ST_SUM1+192)
#define ST_SUM2   (ST_SQ1+192)
#define ST_SQ2    (ST_SUM2+192)
#define ST_SUM3   (ST_SQ2+192)
#define ST_SQ3    (ST_SUM3+768)
#define ST_TOTAL  (ST_SQ3+768)
__device__ __align__(256) float g_stats[ST_TOTAL];

// ================= helpers =================
__device__ __forceinline__ uint32_t f2tf(float f) {
    uint32_t u;
    asm("cvt.rna.tf32.f32 %0, %1;" : "=r"(u) : "f"(f));
    return u;
}
__device__ __forceinline__ float f2tf_f(float f) { return __uint_as_float(f2tf(f)); }

__device__ __forceinline__ void mma_tf32(float* d, const uint32_t* a, const uint32_t* b) {
    asm volatile(
        "mma.sync.aligned.m16n8k8.row.col.f32.tf32.tf32.f32 "
        "{%0,%1,%2,%3}, {%4,%5,%6,%7}, {%8,%9}, {%0,%1,%2,%3};"
        : "+f"(d[0]), "+f"(d[1]), "+f"(d[2]), "+f"(d[3])
        : "r"(a[0]), "r"(a[1]), "r"(a[2]), "r"(a[3]), "r"(b[0]), "r"(b[1]));
}

__device__ __forceinline__ uint32_t smem_u32(const void* p) {
    uint32_t a;
    asm("{ .reg .u64 t; cvta.to.shared.u64 t, %1; cvt.u32.u64 %0, t; }" : "=r"(a) : "l"(p));
    return a;
}
#define CP_ASYNC(dst, src, sz) \
    asm volatile("cp.async.cg.shared.global [%0], [%1], 16, %2;" \
                 :: "r"(dst), "l"(src), "r"(sz) : "memory")
#define CP_COMMIT() asm volatile("cp.async.commit_group;" ::: "memory")
#define CP_WAIT(n)  asm volatile("cp.async.wait_group %0;" :: "n"(n) : "memory")

// ================= TF32 GEMM (unchanged from R13) =================
#define SA 36
#define TILE_U (128*SA)
#define GEMM_DSMEM (2*2*TILE_U*4)

template<int MODE>
__global__ void __launch_bounds__(256, 2) gemm_tc(
    const float* __restrict__ A, int lda,
    const float* __restrict__ W,
    float* __restrict__ C, int Nc, int ldc, int K,
    const float* __restrict__ p0,
    float* __restrict__ psum, float* __restrict__ psq)
{
    extern __shared__ uint32_t dsm[];
    const uint32_t sbase = smem_u32(dsm);

    const int bm = blockIdx.y * 128;
    const int bn = blockIdx.x * 128;
    const int t  = threadIdx.x;
    const int wid  = t >> 5;
    const int lane = t & 31;
    const int qr = lane >> 2;
    const int qc = lane & 3;
    const int warp_m = wid & 3;
    const int warp_n = wid >> 2;

    int kBase = 0, kLen = K;
    if (MODE == 4) { kLen = K >> 1; kBase = blockIdx.z * kLen; }

    const int r0t = t >> 3;
    const int c4  = (t & 7) * 4;

    const float* aRow[4];
    const float* bRow[4];
    int bOk[4];
    uint32_t dstOff[4];
    #pragma unroll
    for (int i = 0; i < 4; i++) {
        int r = r0t + i*32;
        aRow[i] = A + (size_t)(bm + r)*lda + kBase;
        int j = bn + r;
        bOk[i] = (j < Nc);
        bRow[i] = W + (size_t)(bOk[i] ? j : 0)*K + kBase;
        dstOff[i] = (uint32_t)(r*SA + c4) * 4u;
    }

    float acc[2][8][4];
    #pragma unroll
    for (int mt = 0; mt < 2; mt++)
        #pragma unroll
        for (int nt = 0; nt < 8; nt++)
            #pragma unroll
            for (int q = 0; q < 4; q++) acc[mt][nt][q] = 0.f;

    const int NC = (kLen + 31) / 32;

    {
        int k = c4;
        int szA = (k < kLen) ? 16 : 0;
        #pragma unroll
        for (int i = 0; i < 4; i++)
            CP_ASYNC(sbase + dstOff[i], aRow[i] + k, szA);
        #pragma unroll
        for (int i = 0; i < 4; i++) {
            int szB = (bOk[i] && k < kLen) ? 16 : 0;
            CP_ASYNC(sbase + (uint32_t)TILE_U*4 + dstOff[i], bRow[i] + k, szB);
        }
        CP_COMMIT();
    }

    for (int ch = 0; ch < NC; ch++) {
        const int buf = ch & 1;
        if (ch + 1 < NC) {
            const int k = (ch + 1)*32 + c4;
            uint32_t base = sbase + (uint32_t)(buf ^ 1) * 2u * TILE_U * 4u;
            int szA = (k < kLen) ? 16 : 0;
            #pragma unroll
            for (int i = 0; i < 4; i++)
                CP_ASYNC(base + dstOff[i], aRow[i] + k, szA);
            #pragma unroll
            for (int i = 0; i < 4; i++) {
                int szB = (bOk[i] && k < kLen) ? 16 : 0;
                CP_ASYNC(base + (uint32_t)TILE_U*4 + dstOff[i], bRow[i] + k, szB);
            }
            CP_COMMIT();
            CP_WAIT(1);
        } else {
            CP_WAIT(0);
        }
        __syncthreads();

        const uint32_t* As = dsm + (size_t)buf * 2 * TILE_U;
        const uint32_t* Bs = As + TILE_U;
        #pragma unroll
        for (int ks = 0; ks < 4; ks++) {
            const int k0 = ks * 8;
            uint32_t afr[2][4];
            #pragma unroll
            for (int mt = 0; mt < 2; mt++) {
                int r0 = warp_m*32 + mt*16 + qr;
                afr[mt][0] = As[r0*SA + k0 + qc];
                afr[mt][1] = As[(r0+8)*SA + k0 + qc];
                afr[mt][2] = As[r0*SA + k0 + qc + 4];
                afr[mt][3] = As[(r0+8)*SA + k0 + qc + 4];
            }
            uint32_t bfr[8][2];
            #pragma unroll
            for (int nt = 0; nt < 8; nt++) {
                int n = warp_n*64 + nt*8 + qr;
                bfr[nt][0] = Bs[n*SA + k0 + qc];
                bfr[nt][1] = Bs[n*SA + k0 + qc + 4];
            }
            #pragma unroll
            for (int mt = 0; mt < 2; mt++)
                #pragma unroll
                for (int nt = 0; nt < 8; nt++)
                    mma_tf32(acc[mt][nt], afr[mt], bfr[nt]);
        }
        __syncthreads();
    }

    if (MODE == 0 || MODE == 2) {
        #pragma unroll
        for (int mt = 0; mt < 2; mt++) {
            int r0 = bm + warp_m*32 + mt*16 + qr;
            #pragma unroll
            for (int nt = 0; nt < 8; nt++) {
                int c = bn + warp_n*64 + nt*8 + qc*2;
                if (c < Nc) {
                    float v0 = acc[mt][nt][0], v1 = acc[mt][nt][1];
                    float v2 = acc[mt][nt][2], v3 = acc[mt][nt][3];
                    if (MODE == 2) { v0 = f2tf_f(v0); v1 = f2tf_f(v1); v2 = f2tf_f(v2); v3 = f2tf_f(v3); }
                    *(float2*)&C[(size_t)r0*ldc + c]     = make_float2(v0, v1);
                    *(float2*)&C[(size_t)(r0+8)*ldc + c] = make_float2(v2, v3);
                }
            }
        }
    } else if (MODE == 1) {
        #pragma unroll
        for (int mt = 0; mt < 2; mt++) {
            int r0 = bm + warp_m*32 + mt*16 + qr;
            #pragma unroll
            for (int nt = 0; nt < 8; nt++) {
                int c = bn + warp_n*64 + nt*8 + qc*2;
                if (c < Nc) {
                    float b0 = p0[c], b1 = p0[c+1];
                    float v;
                    v = acc[mt][nt][0] + b0; v = (v > 20.f) ? v : log1pf(__expf(v));
                    C[(size_t)r0*ldc + c] = v;
                    v = acc[mt][nt][1] + b1; v = (v > 20.f) ? v : log1pf(__expf(v));
                    C[(size_t)r0*ldc + c + 1] = v;
                    v = acc[mt][nt][2] + b0; v = (v > 20.f) ? v : log1pf(__expf(v));
                    C[(size_t)(r0+8)*ldc + c] = v;
                    v = acc[mt][nt][3] + b1; v = (v > 20.f) ? v : log1pf(__expf(v));
                    C[(size_t)(r0+8)*ldc + c + 1] = v;
                }
            }
        }
    } else if (MODE == 4) {
        #pragma unroll
        for (int mt = 0; mt < 2; mt++) {
            int r0 = bm + warp_m*32 + mt*16 + qr;
            #pragma unroll
            for (int nt = 0; nt < 8; nt++) {
                int c = bn + warp_n*64 + nt*8 + qc*2;
                if (c < Nc) {
                    atomicAdd(&C[(size_t)r0*ldc + c],     acc[mt][nt][0]);
                    atomicAdd(&C[(size_t)r0*ldc + c + 1], acc[mt][nt][1]);
                    atomicAdd(&C[(size_t)(r0+8)*ldc + c],     acc[mt][nt][2]);
                    atomicAdd(&C[(size_t)(r0+8)*ldc + c + 1], acc[mt][nt][3]);
                }
            }
        }
    } else {
        float s[16], ss[16];
        #pragma unroll
        for (int i = 0; i < 16; i++) { s[i] = 0.f; ss[i] = 0.f; }
        #pragma unroll
        for (int mt = 0; mt < 2; mt++) {
            int r0 = bm + warp_m*32 + mt*16 + qr;
            #pragma unroll
            for (int nt = 0; nt < 8; nt++) {
                int c = bn + warp_n*64 + nt*8 + qc*2;
                if (c < Nc) {
                    *(float2*)&C[(size_t)r0*ldc + c]     = make_float2(acc[mt][nt][0], acc[mt][nt][1]);
                    *(float2*)&C[(size_t)(r0+8)*ldc + c] = make_float2(acc[mt][nt][2], acc[mt][nt][3]);
                    #pragma unroll
                    for (int h = 0; h < 2; h++) {
                        float v0 = acc[mt][nt][h], v1 = acc[mt][nt][h+2];
                        s[nt*2+h]  += v0 + v1;
                        ss[nt*2+h] += v0*v0 + v1*v1;
                    }
                }
            }
        }
        #pragma unroll
        for (int o = 4; o < 32; o <<= 1) {
            #pragma unroll
            for (int i = 0; i < 16; i++) {
                s[i]  += __shfl_xor_sync(0xffffffffu, s[i], o);
                ss[i] += __shfl_xor_sync(0xffffffffu, ss[i], o);
            }
        }
        if (qr == 0) {
            #pragma unroll
            for (int nt = 0; nt < 8; nt++)
                #pragma unroll
                for (int h = 0; h < 2; h++) {
                    int c = bn + warp_n*64 + nt*8 + qc*2 + h;
                    if (c < Nc) {
                        atomicAdd(&psum[c], s[nt*2+h]);
                        atomicAdd(&psq[c],  ss[nt*2+h]);
                    }
                }
        }
    }
}

// ---------------- tf32 pre-round ----------------
__global__ void round_tf32(const float* __restrict__ X, float* __restrict__ Y, int n4)
{
    int i = blockIdx.x * blockDim.x + threadIdx.x;
    if (i >= n4) return;
    float4 v = ((const float4*)X)[i];
    v.x = f2tf_f(v.x); v.y = f2tf_f(v.y); v.z = f2tf_f(v.z); v.w = f2tf_f(v.w);
    ((float4*)Y)[i] = v;
}

__global__ void bn_silu(const float* __restrict__ X, float* __restrict__ Y,
                        const float* __restrict__ sum, const float* __restrict__ sq,
                        const float* __restrict__ g, const float* __restrict__ b,
                        int M, int C)
{
    int idx = blockIdx.x * blockDim.x + threadIdx.x;
    if (idx >= M*C) return;
    int c = idx % C;
    float mean = sum[c] / (float)M;
    float var  = sq[c] / (float)M - mean*mean;
    float v = (X[idx] - mean) * rsqrtf(var + EPSq) * g[c] + b[c];
    Y[idx] = f2tf_f(v / (1.f + __expf(-v)));
}

// ---------------- fused: silu(bn1(h0)) staged once in smem -> dwconv5 -> tmpH
//                  + per-channel sum/sq of conv output (bn2 stats) ----------------
// grid (Lq/64, Bq), block 256. smem tile 68 rows x 192 ch.
__global__ void __launch_bounds__(256) dwconv_mega(
    const float* __restrict__ H0, const float* __restrict__ w,
    const float* __restrict__ sum1, const float* __restrict__ sq1,
    const float* __restrict__ g1, const float* __restrict__ b1,
    float* __restrict__ TMPH,
    float* __restrict__ sum2, float* __restrict__ sq2)
{
    __shared__ float tile[68*HIDq];
    __shared__ float cs[HIDq], cq[HIDq];
    const int bb = blockIdx.y;
    const int c0 = blockIdx.x * 64;
    const int t  = threadIdx.x;

    for (int i = t; i < HIDq; i += 256) { cs[i] = 0.f; cq[i] = 0.f; }

    // phase 1: silu(bn1(.)) once per element
    for (int i = t; i < 68*HIDq; i += 256) {
        int row = i / HIDq;           // 0..67
        int ch  = i % HIDq;
        int l   = c0 - 2 + row;
        float v = 0.f;
        if (l >= 0 && l < Lq) {
            float mean = sum1[ch] / (float)Nq;
            float var  = sq1[ch] / (float)Nq - mean*mean;
            float ga = rsqrtf(var + EPSq) * g1[ch];
            float be = b1[ch] - mean*ga;
            float u = H0[(size_t)(bb*Lq + l)*HIDq + ch] * ga + be;
            v = u / (1.f + __expf(-u));
        }
        tile[i] = v;
    }
    __syncthreads();

    // phase 2: conv K=5, accumulate channel stats in smem
    for (int i = t; i < 64*HIDq; i += 256) {
        int row = i / HIDq;           // 0..63 -> l = c0+row
        int ch  = i % HIDq;
        float acc = 0.f;
        #pragma unroll
        for (int k = 0; k < 5; k++)
            acc += tile[(row + k)*HIDq + ch] * w[ch*5 + k];
        TMPH[(size_t)(bb*Lq + c0 + row)*HIDq + ch] = acc;
        atomicAdd(&cs[ch], acc);
        atomicAdd(&cq[ch], acc*acc);
    }
    __syncthreads();
    for (int i = t; i < HIDq; i += 256) {
        atomicAdd(&sum2[i], cs[i]);
        atomicAdd(&sq2[i],  cq[i]);
    }
}

// ---------------- bn_add + LN, fused ----------------
__global__ void __launch_bounds__(256) bn_add_ln(
    const float* __restrict__ E, const float* __restrict__ X,
    const float* __restrict__ sum3, const float* __restrict__ sq3,
    const float* __restrict__ exg, const float* __restrict__ exb,
    const float* __restrict__ lng, const float* __restrict__ lnb,
    float* __restrict__ X1, float* __restrict__ XN,
    float* __restrict__ rm, float* __restrict__ rs)
{
    const int row = blockIdx.x;
    const int tid = threadIdx.x;
    float vloc[3];
    float s = 0.f, ss = 0.f;
    #pragma unroll
    for (int j = 0; j < 3; j++) {
        int c = tid + j*256;
        float mean = sum3[c] / (float)Nq;
        float var  = sq3[c] / (float)Nq - mean*mean;
        float ga = rsqrtf(var + EPSq) * exg[c];
        float be = exb[c] - mean*ga;
        float v = X[(size_t)row*Dq + c] + E[(size_t)row*Dq + c]*ga + be;
        vloc[j] = v;
        s += v; ss += v*v;
    }
    __shared__ float sh1[8], sh2[8], bcast[2];
    for (int o = 16; o; o >>= 1) {
        s  += __shfl_down_sync(0xffffffffu, s, o);
        ss += __shfl_down_sync(0xffffffffu, ss, o);
    }
    int lane = tid & 31, warp = tid >> 5;
    if (lane == 0) { sh1[warp] = s; sh2[warp] = ss; }
    __syncthreads();
    if (tid == 0) {
        s = 0.f; ss = 0.f;
        #pragma unroll
        for (int wv = 0; wv < 8; wv++) { s += sh1[wv]; ss += sh2[wv]; }
        float m = s / (float)Dq;
        float v = ss / (float)Dq - m*m;
        float r = rsqrtf(v + EPSq);
        bcast[0] = m; bcast[1] = r;
        rm[row] = m; rs[row] = r;
    }
    __syncthreads();
    float m = bcast[0], r = bcast[1];
    #pragma unroll
    for (int j = 0; j < 3; j++) {
        int c = tid + j*256;
        X1[(size_t)row*Dq + c] = vloc[j];
        XN[(size_t)row*Dq + c] = f2tf_f((vloc[j] - m) * r * lng[c] + lnb[c]);
    }
}

// ---------------- combine + LN stats, fused ----------------
__global__ void __launch_bounds__(256) combine_ln(
    const float* __restrict__ X, const float* __restrict__ X1,
    const float* __restrict__ MO, const float* __restrict__ GL,
    const float* __restrict__ gb,
    float* __restrict__ XF, float* __restrict__ rm2, float* __restrict__ rs2)
{
    const int row = blockIdx.x;
    const int tid = threadIdx.x;
    float vloc[3];
    float s = 0.f, ss = 0.f;
    #pragma unroll
    for (int j = 0; j < 3; j++) {
        int c = tid + j*256;
        size_t i = (size_t)row*Dq + c;
        float gate = 1.f / (1.f + __expf(-(GL[i] + gb[c])));
        float v = X1[i] + MO[i]*gate + X[i];
        vloc[j] = v;
        s += v; ss += v*v;
    }
    __shared__ float sh1[8], sh2[8];
    for (int o = 16; o; o >>= 1) {
        s  += __shfl_down_sync(0xffffffffu, s, o);
        ss += __shfl_down_sync(0xffffffffu, ss, o);
    }
    int lane = tid & 31, warp = tid >> 5;
    if (lane == 0) { sh1[warp] = s; sh2[warp] = ss; }
    __syncthreads();
    if (tid == 0) {
        s = 0.f; ss = 0.f;
        #pragma unroll
        for (int wv = 0; wv < 8; wv++) { s += sh1[wv]; ss += sh2[wv]; }
        float m = s / (float)Dq;
        float v = ss / (float)Dq - m*m;
        rm2[row] = m;
        rs2[row] = rsqrtf(v + EPSq);
    }
    #pragma unroll
    for (int j = 0; j < 3; j++) {
        int c = tid + j*256;
        XF[(size_t)row*Dq + c] = vloc[j];
    }
}

// ---------------- causal conv K=4 + bias + silu ----------------
__global__ void conv_causal_silu(const float* __restrict__ XZ, const float* __restrict__ w,
                                 const float* __restrict__ bias, float* __restrict__ Y)
{
    int idx = blockIdx.x * blockDim.x + threadIdx.x;
    if (idx >= Nq*DIq) return;
    int c  = idx % DIq;
    int l  = (idx / DIq) % Lq;
    int bb = idx / (DIq*Lq);
    float acc = bias[c];
    #pragma unroll
    for (int k = 0; k < 4; k++) {
        int ls = l - 3 + k;
        if (ls >= 0) acc += XZ[(size_t)(bb*Lq + ls)*(2*DIq) + c] * w[c*4 + k];
    }
    Y[idx] = f2tf_f(acc / (1.f + __expf(-acc)));
}

// feat_attr
__global__ void attr_max(const float* __restrict__ X, const float* __restrict__ mean,
                         const float* __restrict__ rstd, const float* __restrict__ g,
                         const float* __restrict__ b, float* __restrict__ out)
{
    int c  = blockIdx.y * blockDim.x + threadIdx.x;
    int bb = blockIdx.x;
    float gm = g[c], gb = b[c];
    float mx = -3.4e38f;
    for (int l = 0; l < Lq; l++) {
        int row = bb*Lq + l;
        float v = (X[(size_t)row*Dq + c] - mean[row]) * rstd[row] * gm + gb;
        mx = fmaxf(mx, v);
    }
    out[bb*Dq + c] = mx;
}

// ---------------- selective scan ----------------
__global__ void __launch_bounds__(128) scan_k(
    const float* __restrict__ delta, const float* __restrict__ u,
    const float* __restrict__ dbc,   const float* __restrict__ xz,
    const float* __restrict__ A_log, const float* __restrict__ Dp,
    float* __restrict__ y)
{
    __shared__ float Bs[128][DSq];
    __shared__ float Cs[128][DSq];
    const int bb = blockIdx.y;
    const int d  = blockIdx.x * 128 + threadIdx.x;

    float A[DSq], h[DSq];
    bool fast = true;
    #pragma unroll
    for (int s = 0; s < DSq; s++) {
        A[s] = -expf(A_log[d*DSq + s]);
        h[s] = 0.f;
        if (fabsf(A[s] + (float)(s+1)) > 1e-3f * (float)(s+1)) fast = false;
    }
    const float dp = Dp[d];

    for (int c0 = 0; c0 < Lq; c0 += 128) {
        for (int i = threadIdx.x; i < 128*DSq; i += 128) {
            int l = i >> 4, s = i & 15;
            size_t row = (size_t)(bb*Lq + c0 + l);
            Bs[l][s] = dbc[row*80 + DTRq + s];
            Cs[l][s] = dbc[row*80 + DTRq + DSq + s];
        }
        __syncthreads();
        size_t row0 = (size_t)(bb*Lq + c0);
        float dv = delta[row0*DIq + d];
        float uv = u[row0*DIq + d];
        float zv = xz[row0*(2*DIq) + DIq + d];
        if (fast) {
            for (int l = 0; l < 128; l++) {
                float nd = 0.f, nu = 0.f, nz = 0.f;
                if (l < 127) {
                    size_t rn = row0 + l + 1;
                    nd = delta[rn*DIq + d];
                    nu = u[rn*DIq + d];
                    nz = xz[rn*(2*DIq) + DIq + d];
                }
                float du = dv * uv;
                float e1 = __expf(-dv);
                float p = e1;
                float acc = 0.f;
                #pragma unroll
                for (int s = 0; s < DSq; s++) {
                    h[s] = h[s] * p + du * Bs[l][s];
                    acc  = fmaf(h[s], Cs[l][s], acc);
                    p *= e1;
                }
                float sz = zv / (1.f + __expf(-zv));
                y[(row0 + l)*DIq + d] = f2tf_f((acc + uv*dp) * sz);
                dv = nd; uv = nu; zv = nz;
            }
        } else {
            for (int l = 0; l < 128; l++) {
                float nd = 0.f, nu = 0.f, nz = 0.f;
                if (l < 127) {
                    size_t rn = row0 + l + 1;
                    nd = delta[rn*DIq + d];
                    nu = u[rn*DIq + d];
                    nz = xz[rn*(2*DIq) + DIq + d];
                }
                float du = dv * uv;
                float acc = 0.f;
                #pragma unroll
                for (int s = 0; s < DSq; s++) {
                    h[s] = h[s] * __expf(dv * A[s]) + du * Bs[l][s];
                    acc  = fmaf(h[s], Cs[l][s], acc);
                }
                float sz = zv / (1.f + __expf(-zv));
                y[(row0 + l)*DIq + d] = f2tf_f((acc + uv*dp) * sz);
                dv = nd; uv = nu; zv = nz;
            }
        }
        __syncthreads();
    }
}

// feat_id chunked: grid (Bq, 3, 4); atomicAdd partial sums into fid
__global__ void feat_id_k(const float* __restrict__ X, const float* __restrict__ mean,
                          const float* __restrict__ rstd, const float* __restrict__ g,
                          const float* __restrict__ b, float* __restrict__ fid)
{
    int c  = blockIdx.y * blockDim.x + threadIdx.x;
    int bb = blockIdx.x;
    int l0 = blockIdx.z * 128;
    float gm = g[c], gb = b[c];
    float s = 0.f;
    for (int l = l0; l < l0 + 128; l++) {
        int row = bb*Lq + l;
        s += (X[(size_t)row*Dq + c] - mean[row]) * rstd[row] * gm + gb;
    }
    atomicAdd(&fid[bb*Dq + c], s);
}

// feat_bn: emits out2 = fid/L and out3 = bn(fid/L)
__global__ void feat_bn(const float* __restrict__ fid, const float* __restrict__ g,
                        const float* __restrict__ b, float* __restrict__ out2,
                        float* __restrict__ out3)
{
    int c = blockIdx.x * blockDim.x + threadIdx.x;
    if (c >= Dq) return;
    float s = 0.f, ss = 0.f;
    float v[Bq];
    #pragma unroll 4
    for (int bb = 0; bb < Bq; bb++) {
        v[bb] = fid[bb*Dq + c] / (float)Lq;
        s += v[bb]; ss += v[bb]*v[bb];
    }
    float m = s / (float)Bq;
    float var = ss / (float)Bq - m*m;
    float rs = rsqrtf(var + EPSq);
    #pragma unroll 4
    for (int bb = 0; bb < Bq; bb++) {
        out2[bb*Dq + c] = v[bb];
        out3[bb*Dq + c] = (v[bb] - m) * rs * g[c] + b[c];
    }
}

// ---------------- host ----------------
#define GETSYM(p, s) { void* _t; cudaGetSymbolAddress(&_t, s); p = (float*)_t; }

extern "C" void kernel_launch(void* const* d_in, const int* in_sizes, int n_in,
                              void* d_out, int out_size)
{
    const float* x        = (const float*)d_in[0];
    const float* sq_w     = (const float*)d_in[1];
    const float* sq_bn_g  = (const float*)d_in[2];
    const float* sq_bn_b  = (const float*)d_in[3];
    const float* dw_w     = (const float*)d_in[4];
    const float* dw_bn_g  = (const float*)d_in[5];
    const float* dw_bn_b  = (const float*)d_in[6];
    const float* ex_w     = (const float*)d_in[7];
    const float* ex_bn_g  = (const float*)d_in[8];
    const float* ex_bn_b  = (const float*)d_in[9];
    const float* attr_g   = (const float*)d_in[10];
    const float* attr_b   = (const float*)d_in[11];
    const float* mnorm_g  = (const float*)d_in[12];
    const float* mnorm_b  = (const float*)d_in[13];
    const float* in_proj_w= (const float*)d_in[14];
    const float* conv_w   = (const float*)d_in[15];
    const float* conv_b   = (const float*)d_in[16];
    const float* xproj_w  = (const float*)d_in[17];
    const float* dtproj_w = (const float*)d_in[18];
    const float* dtproj_b = (const float*)d_in[19];
    const float* A_log    = (const float*)d_in[20];
    const float* D_param  = (const float*)d_in[21];
    const float* out_proj_w = (const float*)d_in[22];
    const float* gate_w   = (const float*)d_in[23];
    const float* gate_b   = (const float*)d_in[24];
    const float* idn_g    = (const float*)d_in[25];
    const float* idn_b    = (const float*)d_in[26];
    const float* idbn_g   = (const float*)d_in[27];
    const float* idbn_b   = (const float*)d_in[28];
    float* out = (float*)d_out;

    float *h0,*tmpH,*h2,*e,*x1,*xn,*xz,*xm2,*dbc,*del,*y,*mo,*gl,*xf;
    float *rm,*rs,*rm2,*rs2,*fid,*stats,*xr,*wr;
    GETSYM(h0, g_h0);   GETSYM(tmpH, g_tmpH); GETSYM(h2, g_h2);
    GETSYM(e, g_e);     GETSYM(x1, g_x1);     GETSYM(xn, g_xn);
    GETSYM(xz, g_xz);   GETSYM(xm2, g_xm2);   GETSYM(dbc, g_dbc);
    GETSYM(del, g_del); GETSYM(y, g_y);       GETSYM(mo, g_mo);
    GETSYM(gl, g_gl);   GETSYM(xf, g_xf);
    GETSYM(rm, g_rm);   GETSYM(rs, g_rs);     GETSYM(rm2, g_rm2); GETSYM(rs2, g_rs2);
    GETSYM(fid, g_fid); GETSYM(stats, g_stats);
    GETSYM(xr, g_xr);   GETSYM(wr, g_wr);

    float* sum1 = stats + ST_SUM1;
    float* sq1  = stats + ST_SQ1;
    float* sum2 = stats + ST_SUM2;
    float* sq2  = stats + ST_SQ2;
    float* sum3 = stats + ST_SUM3;
    float* sq3  = stats + ST_SQ3;

    static cudaStream_t s1 = 0;
    static cudaEvent_t evW0 = 0, evWdone = 0, evFork = 0, evZ = 0, evJoin = 0;
    static int smemSet = 0;
    if (!s1) {
        cudaStreamCreateWithFlags(&s1, cudaStreamNonBlocking);
        cudaEventCreateWithFlags(&evW0, cudaEventDisableTiming);
        cudaEventCreateWithFlags(&evWdone, cudaEventDisableTiming);
        cudaEventCreateWithFlags(&evFork, cudaEventDisableTiming);
        cudaEventCreateWithFlags(&evZ, cudaEventDisableTiming);
        cudaEventCreateWithFlags(&evJoin, cudaEventDisableTiming);
    }
    if (!smemSet) {
        cudaFuncSetAttribute(gemm_tc<0>, cudaFuncAttributeMaxDynamicSharedMemorySize, GEMM_DSMEM);
        cudaFuncSetAttribute(gemm_tc<1>, cudaFuncAttributeMaxDynamicSharedMemorySize, GEMM_DSMEM);
        cudaFuncSetAttribute(gemm_tc<2>, cudaFuncAttributeMaxDynamicSharedMemorySize, GEMM_DSMEM);
        cudaFuncSetAttribute(gemm_tc<3>, cudaFuncAttributeMaxDynamicSharedMemorySize, GEMM_DSMEM);
        cudaFuncSetAttribute(gemm_tc<4>, cudaFuncAttributeMaxDynamicSharedMemorySize, GEMM_DSMEM);
        smemSet = 1;
    }

    const int T = 256;
    dim3 gHID((Nq*HIDq + T-1)/T), gDI((Nq*DIq + T-1)/T);

    cudaMemsetAsync(stats, 0, ST_TOTAL*sizeof(float));
    cudaMemsetAsync(dbc, 0, (size_t)Nq*80*sizeof(float));
    cudaMemsetAsync(fid, 0, (size_t)Bq*Dq*sizeof(float));

    // 0) rounds needed on main: x, sq_w, ex_w
    round_tf32<<<(Nq*Dq/4 + 255)/256, 256>>>(x, xr, Nq*Dq/4);
    round_tf32<<<(HIDq*Dq/4 + 255)/256, 256>>>(sq_w, wr + W_SQ, HIDq*Dq/4);
    round_tf32<<<(Dq*HIDq/4 + 255)/256, 256>>>(ex_w, wr + W_EX, Dq*HIDq/4);
    cudaEventRecord(evW0, 0);
    cudaStreamWaitEvent(s1, evW0, 0);
    round_tf32<<<(2*DIq*Dq/4 + 255)/256, 256, 0, s1>>>(in_proj_w, wr + W_INP, 2*DIq*Dq/4);
    round_tf32<<<(80*DIq/4 + 255)/256, 256, 0, s1>>>(xproj_w,  wr + W_XP,  80*DIq/4);
    round_tf32<<<(DIq*DTRq/4 + 255)/256, 256, 0, s1>>>(dtproj_w, wr + W_DT, DIq*DTRq/4);
    round_tf32<<<(Dq*DIq/4 + 255)/256, 256, 0, s1>>>(out_proj_w, wr + W_OUT, Dq*DIq/4);
    round_tf32<<<(Dq*Dq/4 + 255)/256, 256, 0, s1>>>(gate_w, wr + W_GATE, Dq*Dq/4);
    cudaEventRecord(evWdone, s1);

    // 1) squeeze GEMM (fused BN stats)
    gemm_tc<3><<<dim3(2, Nq/128), 256, GEMM_DSMEM>>>(xr, Dq, wr + W_SQ, h0, HIDq, HIDq, Dq, 0, sum1, sq1);

    // 2) fused silu(bn1)+dwconv5+bn2-stats; then bn_silu2 -> h2
    dwconv_mega<<<dim3(Lq/64, Bq), T>>>(h0, dw_w, sum1, sq1, sq_bn_g, sq_bn_b,
                                        tmpH, sum2, sq2);
    bn_silu<<<gHID, T>>>(tmpH, h2, sum2, sq2, dw_bn_g, dw_bn_b, Nq, HIDq);

    // 3) excite GEMM (fused BN stats) + fused bn_add + LN
    gemm_tc<3><<<dim3(6, Nq/128), 256, GEMM_DSMEM>>>(h2, HIDq, wr + W_EX, e, Dq, Dq, HIDq, 0, sum3, sq3);
    bn_add_ln<<<Nq, T>>>(e, x, sum3, sq3, ex_bn_g, ex_bn_b, mnorm_g, mnorm_b,
                         x1, xn, rm, rs);

    // fork: side stream z-half of in_proj, feat_attr, gate GEMM
    cudaEventRecord(evFork, 0);
    cudaStreamWaitEvent(s1, evFork, 0);
    gemm_tc<0><<<dim3(12, Nq/128), 256, GEMM_DSMEM, s1>>>(
        xn, Dq, wr + W_INP + (size_t)DIq*Dq, xz + DIq, DIq, 2*DIq, Dq, 0, 0, 0);
    cudaEventRecord(evZ, s1);
    attr_max<<<dim3(Bq,3), T, 0, s1>>>(x1, rm, rs, attr_g, attr_b, out);
    gemm_tc<0><<<dim3(6, Nq/128), 256, GEMM_DSMEM, s1>>>(xn, Dq, wr + W_GATE, gl, Dq, Dq, Dq, 0, 0, 0);
    cudaEventRecord(evJoin, s1);

    // 5) main: xm-half of in_proj
    cudaStreamWaitEvent(0, evWdone, 0);
    gemm_tc<0><<<dim3(12, Nq/128), 256, GEMM_DSMEM>>>(
        xn, Dq, wr + W_INP, xz, DIq, 2*DIq, Dq, 0, 0, 0);

    // 6) causal conv + silu
    conv_causal_silu<<<gDI, T>>>(xz, conv_w, conv_b, xm2);

    // 7) x_proj split-K=2 + re-round; dt_proj (+softplus)
    gemm_tc<4><<<dim3(1, Nq/128, 2), 256, GEMM_DSMEM>>>(xm2, DIq, wr + W_XP, dbc, 80, 80, DIq, 0, 0, 0);
    round_tf32<<<(Nq*80/4 + 255)/256, 256>>>(dbc, dbc, Nq*80/4);
    gemm_tc<1><<<dim3(12, Nq/128), 256, GEMM_DSMEM>>>(dbc, 80, wr + W_DT, del, DIq, DIq, DTRq, dtproj_b, 0, 0);

    // 8) selective scan
    cudaStreamWaitEvent(0, evZ, 0);
    scan_k<<<dim3(DIq/128, Bq), 128>>>(del, xm2, dbc, xz, A_log, D_param, y);

    // 9) out_proj; join gate; fused combine + LN stats
    gemm_tc<0><<<dim3(6, Nq/128), 256, GEMM_DSMEM>>>(y, DIq, wr + W_OUT, mo, Dq, Dq, DIq, 0, 0, 0);
    cudaStreamWaitEvent(0, evJoin, 0);
    combine_ln<<<Nq, T>>>(x, x1, mo, gl, gate_b, xf, rm2, rs2);

    // 10) feat_id (chunked) + feat_bn
    feat_id_k<<<dim3(Bq,3,4), T>>>(xf, rm2, rs2, idn_g, idn_b, fid);
    feat_bn<<<3, T>>>(fid, idbn_g, idbn_b, out + Bq*Dq, out + 2*Bq*Dq);
}